// round 1
// baseline (speedup 1.0000x reference)
#include <cuda_runtime.h>
#include <math.h>

// ---------------------------------------------------------------------------
// MiniGRUConv2d4: 3x(conv3x3+BN[+sigmoid]) -> 4 directional affine scans ->
// weighted combine.
// Shapes: B=4, Cin=64, C4=256 (4 groups of 64), H=W=256.
//
// Scratch: g_zhs[set][b][ch][y][x], set 0=z(sigmoid), 1=h(raw), 2=s(sigmoid)
// ---------------------------------------------------------------------------

#define B_  4
#define CIN 64
#define C4  256
#define HH  256
#define WW  256

static __device__ float g_zhs[(size_t)3 * B_ * C4 * HH * WW]; // 805 MB scratch

struct ConvParams {
    const float* w[3];
    const float* g[3];
    const float* b[3];
    const float* m[3];
    const float* v[3];
};

// ---------------------------------------------------------------------------
// Conv kernel: tile 32(x) x 8(y), 32 couts per block.
// 256 threads: lane (0..31) = x within tile, cog (0..7) = cout group of 4.
// Each thread: 8 consecutive y pixels x 4 couts = 32 fp32 accumulators.
// cin staged in chunks of 8 through shared memory.
// ---------------------------------------------------------------------------
__global__ __launch_bounds__(256, 2)
void conv_bn_kernel(const float* __restrict__ xs, ConvParams P)
{
    const int tid  = threadIdx.x;
    const int lane = tid & 31;
    const int cog  = tid >> 5;

    const int b       = blockIdx.z / 24;
    const int cb      = blockIdx.z % 24;
    const int co_base = cb * 32;             // 0..736 over the 768 fused couts
    const int set     = co_base >> 8;        // 0=z,1=h,2=s
    const int co_set0 = co_base & 255;       // base within the 256-ch set

    const int x_base = blockIdx.x * 32;
    const int y_base = blockIdx.y * 8;

    __shared__ float s_in[8][10][35];        // [ci][row][col] (+1 pad)
    __shared__ float s_w[32][8][9];          // [co][ci][k]

    float acc[8][4];
#pragma unroll
    for (int py = 0; py < 8; ++py)
#pragma unroll
        for (int c = 0; c < 4; ++c) acc[py][c] = 0.f;

    const float* __restrict__ wset = P.w[set];

    for (int cc = 0; cc < 8; ++cc) {
        const int ci0 = cc * 8;

        // stage input tile (10 rows x 34 cols x 8 ci), zero-padded at borders
        for (int idx = tid; idx < 8 * 10 * 34; idx += 256) {
            int ci  = idx / 340;
            int rem = idx - ci * 340;
            int row = rem / 34;
            int col = rem - row * 34;
            int y = y_base - 1 + row;
            int x = x_base - 1 + col;
            float val = 0.f;
            if ((unsigned)y < 256u && (unsigned)x < 256u)
                val = xs[(((size_t)b * CIN + (ci0 + ci)) << 16) + (y << 8) + x];
            s_in[ci][row][col] = val;
        }
        // stage weights (32 co x 8 ci x 9)
        for (int idx = tid; idx < 32 * 8 * 9; idx += 256) {
            int co  = idx / 72;
            int rem = idx - co * 72;
            int ci  = rem / 9;
            int k   = rem - ci * 9;
            s_w[co][ci][k] = wset[((size_t)(co_set0 + co) * CIN + (ci0 + ci)) * 9 + k];
        }
        __syncthreads();

#pragma unroll
        for (int ci = 0; ci < 8; ++ci) {
            float wr[4][9];
#pragma unroll
            for (int c = 0; c < 4; ++c)
#pragma unroll
                for (int k = 0; k < 9; ++k)
                    wr[c][k] = s_w[cog * 4 + c][ci][k];

#pragma unroll
            for (int row = 0; row < 10; ++row) {
                float v0 = s_in[ci][row][lane];
                float v1 = s_in[ci][row][lane + 1];
                float v2 = s_in[ci][row][lane + 2];
#pragma unroll
                for (int ky = 0; ky < 3; ++ky) {
                    const int py = row - ky;   // tile output row
                    if (py >= 0 && py < 8) {
#pragma unroll
                        for (int c = 0; c < 4; ++c) {
                            acc[py][c] = fmaf(v0, wr[c][ky * 3 + 0], acc[py][c]);
                            acc[py][c] = fmaf(v1, wr[c][ky * 3 + 1], acc[py][c]);
                            acc[py][c] = fmaf(v2, wr[c][ky * 3 + 2], acc[py][c]);
                        }
                    }
                }
            }
        }
        __syncthreads();
    }

    // epilogue: BN affine (+ sigmoid for sets 0,2), store to scratch
#pragma unroll
    for (int c = 0; c < 4; ++c) {
        const int co = co_set0 + cog * 4 + c;
        float gamma = P.g[set][co];
        float beta  = P.b[set][co];
        float mean  = P.m[set][co];
        float var   = P.v[set][co];
        float inv   = gamma * rsqrtf(var + 1e-5f);
        float bias  = beta - mean * inv;
        size_t base = ((((size_t)set * B_ + b) * C4 + co) << 16) + (x_base + lane);
#pragma unroll
        for (int py = 0; py < 8; ++py) {
            float vv = acc[py][c] * inv + bias;
            if (set != 1) vv = 1.f / (1.f + expf(-vv));
            g_zhs[base + ((size_t)(y_base + py) << 8)] = vv;
        }
    }
}

// ---------------------------------------------------------------------------
// Vertical scans (groups 0 fwd / 1 bwd along H), fused with s-weighted write.
// One thread per (b, c, x) column; pass 1 writes out, pass 2 accumulates.
// ---------------------------------------------------------------------------
__global__ void scan_v_kernel(const float* __restrict__ h20,
                              const float* __restrict__ h21,
                              float* __restrict__ out)
{
    int t = blockIdx.x * 256 + threadIdx.x;   // 65536 threads
    int x = t & 255;
    int c = (t >> 8) & 63;
    int b = t >> 14;

    size_t zb = ((((size_t)0 * B_ + b) * C4 + c) << 16) + x;
    size_t hb = ((((size_t)1 * B_ + b) * C4 + c) << 16) + x;
    size_t sb = ((((size_t)2 * B_ + b) * C4 + c) << 16) + x;
    size_t ob = (((size_t)b * 64 + c) << 16) + x;

    // group 0: forward along y
    float carry = h20[c];
    for (int y = 0; y < 256; ++y) {
        size_t off = (size_t)y << 8;
        float z  = g_zhs[zb + off];
        float hv = g_zhs[hb + off];
        float s  = g_zhs[sb + off];
        carry = z * hv + (1.f - z) * carry;
        out[ob + off] = s * carry;
    }
    // group 1: backward along y (channels +64)
    const size_t coff = (size_t)64 << 16;
    zb += coff; hb += coff; sb += coff;
    carry = h21[c];
    for (int y = 255; y >= 0; --y) {
        size_t off = (size_t)y << 8;
        float z  = g_zhs[zb + off];
        float hv = g_zhs[hb + off];
        float s  = g_zhs[sb + off];
        carry = z * hv + (1.f - z) * carry;
        out[ob + off] += s * carry;
    }
}

// ---------------------------------------------------------------------------
// Horizontal scans (groups 2 fwd / 3 bwd along W) via block-wide affine
// Hillis-Steele scan. One block per (b, c, y) row, thread x = column.
// ---------------------------------------------------------------------------
__global__ void scan_h_kernel(const float* __restrict__ h30,
                              const float* __restrict__ h31,
                              float* __restrict__ out)
{
    int blk = blockIdx.x;      // 65536 rows
    int y = blk & 255;
    int c = (blk >> 8) & 63;
    int b = blk >> 14;
    int x = threadIdx.x;

    __shared__ float sA[256];
    __shared__ float sB[256];

    const size_t rowoff = ((size_t)y << 8) + x;
    auto idx = [&](int set, int ch) {
        return ((((size_t)set * B_ + b) * C4 + ch) << 16) + rowoff;
    };

    // ---- group 2: forward along x, channels 128+c ----
    {
        float z  = g_zhs[idx(0, 128 + c)];
        float hv = g_zhs[idx(1, 128 + c)];
        sA[x] = 1.f - z;
        sB[x] = z * hv;
    }
    float s2 = g_zhs[idx(2, 128 + c)];
    __syncthreads();
#pragma unroll
    for (int off = 1; off < 256; off <<= 1) {
        float a2 = sA[x], b2 = sB[x];
        float a1 = 1.f, b1 = 0.f;
        if (x >= off) { a1 = sA[x - off]; b1 = sB[x - off]; }
        __syncthreads();
        sA[x] = a2 * a1;
        sB[x] = fmaf(a2, b1, b2);
        __syncthreads();
    }
    float accv = s2 * fmaf(sA[x], h30[c], sB[x]);
    __syncthreads();

    // ---- group 3: reverse along x, channels 192+c (scan reversed array) ----
    const int xr = 255 - x;
    {
        float z  = g_zhs[idx(0, 192 + c)];
        float hv = g_zhs[idx(1, 192 + c)];
        sA[xr] = 1.f - z;
        sB[xr] = z * hv;
    }
    float s3 = g_zhs[idx(2, 192 + c)];
    __syncthreads();
#pragma unroll
    for (int off = 1; off < 256; off <<= 1) {
        float a2 = sA[x], b2 = sB[x];
        float a1 = 1.f, b1 = 0.f;
        if (x >= off) { a1 = sA[x - off]; b1 = sB[x - off]; }
        __syncthreads();
        sA[x] = a2 * a1;
        sB[x] = fmaf(a2, b1, b2);
        __syncthreads();
    }
    accv += s3 * fmaf(sA[xr], h31[c], sB[xr]);

    size_t o = (((size_t)b * 64 + c) << 16) + rowoff;
    out[o] += accv;
}

// ---------------------------------------------------------------------------
extern "C" void kernel_launch(void* const* d_in, const int* in_sizes, int n_in,
                              void* d_out, int out_size)
{
    const float* xs = (const float*)d_in[0];

    ConvParams P;
    // order: xs, [w g b m v]_z, [w g b m v]_h, [w g b m v]_s, h20,h21,h30,h31
    for (int s = 0; s < 3; ++s) {
        int base = 1 + s * 5;
        P.w[s] = (const float*)d_in[base + 0];
        P.g[s] = (const float*)d_in[base + 1];
        P.b[s] = (const float*)d_in[base + 2];
        P.m[s] = (const float*)d_in[base + 3];
        P.v[s] = (const float*)d_in[base + 4];
    }
    const float* h20 = (const float*)d_in[16];
    const float* h21 = (const float*)d_in[17];
    const float* h30 = (const float*)d_in[18];
    const float* h31 = (const float*)d_in[19];

    float* out = (float*)d_out;

    dim3 cgrid(8, 32, 96);           // x tiles, y tiles, b(4) * co_blocks(24)
    conv_bn_kernel<<<cgrid, 256>>>(xs, P);

    scan_v_kernel<<<256, 256>>>(h20, h21, out);
    scan_h_kernel<<<65536, 256>>>(h30, h31, out);
}

// round 2
// speedup vs baseline: 2.0947x; 2.0947x over previous
#include <cuda_runtime.h>
#include <math.h>
#include <stdint.h>

// ---------------------------------------------------------------------------
// MiniGRUConv2d4 on GB300:
//   3x(conv3x3 + BN [+sigmoid]) as ONE implicit GEMM on tensor cores (tf32
//   mma.sync), BN folded into weights; then 4 directional affine scans with
//   fused s-weighted combine.
// Shapes: B=4, Cin=64, C4=256 (4 groups of 64ch), H=W=256.
// GEMM: M=768 (3 sets x 256 couts), K=576 ((ky,kx)*64+ci), N=256*256 pixels/b.
// ---------------------------------------------------------------------------

#define B_  4
#define CIN 64
#define C4  256

static __device__ float g_zhs[(size_t)3 * B_ * C4 * 256 * 256]; // z/h/s planes
static __device__ float gWt[768 * 576];                         // transformed W
static __device__ float gBias[768];

struct ConvParams {
    const float* w[3];
    const float* g[3];
    const float* b[3];
    const float* m[3];
    const float* v[3];
};

// ---------------------------------------------------------------------------
// MUFU-free sigmoid: sigma(x) = 1 / (1 + 2^(-x*log2(e)))
// 2^f via degree-6 Taylor on f in [-0.5,0.5] + exponent bit splice;
// reciprocal via bit-hack seed + 3 Newton steps. All FMA/ALU pipe.
// ---------------------------------------------------------------------------
__device__ __forceinline__ float fast_sigmoid(float x)
{
    float u = -1.44269504f * x;
    u = fminf(fmaxf(u, -60.f), 60.f);
    float fi = rintf(u);
    float f  = u - fi;
    float p = 1.54035304e-4f;               // (ln2)^6/720
    p = fmaf(p, f, 1.33335581e-3f);         // (ln2)^5/120
    p = fmaf(p, f, 9.61812910e-3f);         // (ln2)^4/24
    p = fmaf(p, f, 5.55041087e-2f);         // (ln2)^3/6
    p = fmaf(p, f, 2.40226507e-1f);         // (ln2)^2/2
    p = fmaf(p, f, 6.93147181e-1f);         // ln2
    p = fmaf(p, f, 1.0f);
    int ei = (int)fi;
    float e = __int_as_float(__float_as_int(p) + (ei << 23));
    float d = 1.0f + e;
    float r = __int_as_float(0x7EF311C3 - __float_as_int(d));
    r = r * (2.0f - d * r);
    r = r * (2.0f - d * r);
    r = r * (2.0f - d * r);
    return r;
}

// ---------------------------------------------------------------------------
// Prep: fold BN scale into weights, reorder to [co_g][k = (ky*3+kx)*64 + ci],
// round to tf32; compute bias[co_g] = beta - mean*inv.
// ---------------------------------------------------------------------------
__global__ void prep_kernel(ConvParams P)
{
    int idx = blockIdx.x * 256 + threadIdx.x;
    if (idx < 768) {
        int set = idx >> 8, co = idx & 255;
        float inv = P.g[set][co] * rsqrtf(P.v[set][co] + 1e-5f);
        gBias[idx] = P.b[set][co] - P.m[set][co] * inv;
    }
    if (idx < 768 * 576) {
        int co_g = idx / 576;
        int k    = idx - co_g * 576;
        int r    = k >> 6;
        int ci   = k & 63;
        int set  = co_g >> 8;
        int co   = co_g & 255;
        float inv = P.g[set][co] * rsqrtf(P.v[set][co] + 1e-5f);
        float v = P.w[set][(co * 64 + ci) * 9 + r] * inv;
        uint32_t u;
        asm("cvt.rna.tf32.f32 %0, %1;" : "=r"(u) : "f"(v));
        gWt[idx] = __uint_as_float(u);
    }
}

// ---------------------------------------------------------------------------
// Implicit-GEMM conv on tf32 mma.sync.m16n8k8.
// Block: 128 co x 128 px, BK=16, 256 threads (8 warps, 4x2 of 32co x 64px).
// Double-buffered smem; A smem [co][k] stride 20, B smem [k][n] stride 136.
// ---------------------------------------------------------------------------
#define BK    16
#define ASTR  20
#define BSTR  136

__global__ __launch_bounds__(256, 2)
void conv_mma_kernel(const float* __restrict__ xs)
{
    __shared__ uint32_t As[2][128 * ASTR];
    __shared__ uint32_t Bs[2][BK * BSTR];

    const int tid = threadIdx.x;
    const int l   = tid & 31;
    const int w   = tid >> 5;
    const int wm  = w >> 1;            // 0..3
    const int wn  = w & 1;             // 0..1

    const int ntile = blockIdx.x;      // 0..511
    const int m0    = blockIdx.y << 7; // 0..640
    const int b     = blockIdx.z;
    const int y0    = ntile >> 1;
    const int x0    = (ntile & 1) << 7;

    float aR[8], bR[8];

    auto loadA = [&](int kt) {
#pragma unroll
        for (int i = 0; i < 8; ++i) {
            int e  = tid + (i << 8);
            int kk = e & 15, co = e >> 4;
            aR[i] = gWt[(size_t)(m0 + co) * 576 + kt * 16 + kk];
        }
    };
    auto loadB = [&](int kt) {
#pragma unroll
        for (int i = 0; i < 8; ++i) {
            int e  = tid + (i << 8);
            int nn = e & 127, kk = e >> 7;
            int kg = kt * 16 + kk;
            int r  = kg >> 6, ci = kg & 63;
            int r3 = r / 3;
            int dy = r3 - 1, dx = r - r3 * 3 - 1;
            int row = y0 + dy;
            int xx  = x0 + nn + dx;
            float v = 0.f;
            if ((unsigned)row < 256u && (unsigned)xx < 256u)
                v = xs[(((size_t)b * CIN + ci) << 16) + (row << 8) + xx];
            bR[i] = v;
        }
    };
    auto stage = [&](int buf) {
#pragma unroll
        for (int i = 0; i < 8; ++i) {
            int e = tid + (i << 8);
            As[buf][(e >> 4) * ASTR + (e & 15)] = __float_as_uint(aR[i]);
            uint32_t u;
            asm("cvt.rna.tf32.f32 %0, %1;" : "=r"(u) : "f"(bR[i]));
            Bs[buf][(e >> 7) * BSTR + (e & 127)] = u;
        }
    };

    float acc[2][8][4];
#pragma unroll
    for (int mt = 0; mt < 2; ++mt)
#pragma unroll
        for (int nt = 0; nt < 8; ++nt)
#pragma unroll
            for (int c = 0; c < 4; ++c) acc[mt][nt][c] = 0.f;

    loadA(0); loadB(0); stage(0);
    __syncthreads();

    int cur = 0;
    for (int kt = 0; kt < 36; ++kt) {
        if (kt < 35) { loadA(kt + 1); loadB(kt + 1); }

#pragma unroll
        for (int ks = 0; ks < 2; ++ks) {
            const int kb = (ks << 3) + (l & 3);
            uint32_t a[2][4];
#pragma unroll
            for (int mt = 0; mt < 2; ++mt) {
                int mb = (wm << 5) + (mt << 4) + (l >> 2);
                a[mt][0] = As[cur][mb * ASTR + kb];
                a[mt][1] = As[cur][(mb + 8) * ASTR + kb];
                a[mt][2] = As[cur][mb * ASTR + kb + 4];
                a[mt][3] = As[cur][(mb + 8) * ASTR + kb + 4];
            }
#pragma unroll
            for (int nt = 0; nt < 8; ++nt) {
                int nb = (wn << 6) + (nt << 3) + (l >> 2);
                uint32_t b0 = Bs[cur][kb * BSTR + nb];
                uint32_t b1 = Bs[cur][(kb + 4) * BSTR + nb];
#pragma unroll
                for (int mt = 0; mt < 2; ++mt) {
                    asm volatile(
                        "mma.sync.aligned.m16n8k8.row.col.f32.tf32.tf32.f32 "
                        "{%0,%1,%2,%3}, {%4,%5,%6,%7}, {%8,%9}, {%0,%1,%2,%3};"
                        : "+f"(acc[mt][nt][0]), "+f"(acc[mt][nt][1]),
                          "+f"(acc[mt][nt][2]), "+f"(acc[mt][nt][3])
                        : "r"(a[mt][0]), "r"(a[mt][1]),
                          "r"(a[mt][2]), "r"(a[mt][3]),
                          "r"(b0), "r"(b1));
                }
            }
        }
        __syncthreads();
        if (kt < 35) stage(cur ^ 1);
        __syncthreads();
        cur ^= 1;
    }

    // epilogue: + bias, sigmoid for sets 0/2, write scratch planes
    const int set = m0 >> 8;
#pragma unroll
    for (int mt = 0; mt < 2; ++mt) {
#pragma unroll
        for (int rr = 0; rr < 2; ++rr) {
            int co_g = m0 + (wm << 5) + (mt << 4) + (l >> 2) + rr * 8;
            float bias = gBias[co_g];
            int ch = co_g & 255;
            size_t base = ((((size_t)set * B_ + b) * C4 + ch) << 16)
                        + ((size_t)y0 << 8);
#pragma unroll
            for (int nt = 0; nt < 8; ++nt) {
                int xx = x0 + (wn << 6) + (nt << 3) + ((l & 3) << 1);
                float v0 = acc[mt][nt][rr * 2 + 0] + bias;
                float v1 = acc[mt][nt][rr * 2 + 1] + bias;
                if (set != 1) { v0 = fast_sigmoid(v0); v1 = fast_sigmoid(v1); }
                g_zhs[base + xx]     = v0;
                g_zhs[base + xx + 1] = v1;
            }
        }
    }
}

// ---------------------------------------------------------------------------
// Vertical scans (groups 0 fwd / 1 bwd along H), fused s-weighted combine.
// ---------------------------------------------------------------------------
__global__ void scan_v_kernel(const float* __restrict__ h20,
                              const float* __restrict__ h21,
                              float* __restrict__ out)
{
    int t = blockIdx.x * 256 + threadIdx.x;   // 65536 threads
    int x = t & 255;
    int c = (t >> 8) & 63;
    int b = t >> 14;

    size_t zb = ((((size_t)0 * B_ + b) * C4 + c) << 16) + x;
    size_t hb = ((((size_t)1 * B_ + b) * C4 + c) << 16) + x;
    size_t sb = ((((size_t)2 * B_ + b) * C4 + c) << 16) + x;
    size_t ob = (((size_t)b * 64 + c) << 16) + x;

    float carry = h20[c];
    for (int y = 0; y < 256; ++y) {
        size_t off = (size_t)y << 8;
        float z  = g_zhs[zb + off];
        float hv = g_zhs[hb + off];
        float s  = g_zhs[sb + off];
        carry = z * hv + (1.f - z) * carry;
        out[ob + off] = s * carry;
    }
    const size_t coff = (size_t)64 << 16;
    zb += coff; hb += coff; sb += coff;
    carry = h21[c];
    for (int y = 255; y >= 0; --y) {
        size_t off = (size_t)y << 8;
        float z  = g_zhs[zb + off];
        float hv = g_zhs[hb + off];
        float s  = g_zhs[sb + off];
        carry = z * hv + (1.f - z) * carry;
        out[ob + off] += s * carry;
    }
}

// ---------------------------------------------------------------------------
// Horizontal scans (groups 2 fwd / 3 bwd along W) via block-wide affine scan.
// ---------------------------------------------------------------------------
__global__ void scan_h_kernel(const float* __restrict__ h30,
                              const float* __restrict__ h31,
                              float* __restrict__ out)
{
    int blk = blockIdx.x;      // 65536 rows
    int y = blk & 255;
    int c = (blk >> 8) & 63;
    int b = blk >> 14;
    int x = threadIdx.x;

    __shared__ float sA[256];
    __shared__ float sB[256];

    const size_t rowoff = ((size_t)y << 8) + x;
    auto idx = [&](int set, int ch) {
        return ((((size_t)set * B_ + b) * C4 + ch) << 16) + rowoff;
    };

    {
        float z  = g_zhs[idx(0, 128 + c)];
        float hv = g_zhs[idx(1, 128 + c)];
        sA[x] = 1.f - z;
        sB[x] = z * hv;
    }
    float s2 = g_zhs[idx(2, 128 + c)];
    __syncthreads();
#pragma unroll
    for (int off = 1; off < 256; off <<= 1) {
        float a2 = sA[x], b2 = sB[x];
        float a1 = 1.f, b1 = 0.f;
        if (x >= off) { a1 = sA[x - off]; b1 = sB[x - off]; }
        __syncthreads();
        sA[x] = a2 * a1;
        sB[x] = fmaf(a2, b1, b2);
        __syncthreads();
    }
    float accv = s2 * fmaf(sA[x], h30[c], sB[x]);
    __syncthreads();

    const int xr = 255 - x;
    {
        float z  = g_zhs[idx(0, 192 + c)];
        float hv = g_zhs[idx(1, 192 + c)];
        sA[xr] = 1.f - z;
        sB[xr] = z * hv;
    }
    float s3 = g_zhs[idx(2, 192 + c)];
    __syncthreads();
#pragma unroll
    for (int off = 1; off < 256; off <<= 1) {
        float a2 = sA[x], b2 = sB[x];
        float a1 = 1.f, b1 = 0.f;
        if (x >= off) { a1 = sA[x - off]; b1 = sB[x - off]; }
        __syncthreads();
        sA[x] = a2 * a1;
        sB[x] = fmaf(a2, b1, b2);
        __syncthreads();
    }
    accv += s3 * fmaf(sA[xr], h31[c], sB[xr]);

    size_t o = (((size_t)b * 64 + c) << 16) + rowoff;
    out[o] += accv;
}

// ---------------------------------------------------------------------------
extern "C" void kernel_launch(void* const* d_in, const int* in_sizes, int n_in,
                              void* d_out, int out_size)
{
    const float* xs = (const float*)d_in[0];

    ConvParams P;
    for (int s = 0; s < 3; ++s) {
        int base = 1 + s * 5;
        P.w[s] = (const float*)d_in[base + 0];
        P.g[s] = (const float*)d_in[base + 1];
        P.b[s] = (const float*)d_in[base + 2];
        P.m[s] = (const float*)d_in[base + 3];
        P.v[s] = (const float*)d_in[base + 4];
    }
    const float* h20 = (const float*)d_in[16];
    const float* h21 = (const float*)d_in[17];
    const float* h30 = (const float*)d_in[18];
    const float* h31 = (const float*)d_in[19];

    float* out = (float*)d_out;

    prep_kernel<<<1728, 256>>>(P);

    dim3 cgrid(512, 6, 4);
    conv_mma_kernel<<<cgrid, 256>>>(xs);

    scan_v_kernel<<<256, 256>>>(h20, h21, out);
    scan_h_kernel<<<65536, 256>>>(h30, h31, out);
}

// round 4
// speedup vs baseline: 2.7590x; 1.3171x over previous
#include <cuda_runtime.h>
#include <cuda_fp16.h>
#include <math.h>
#include <stdint.h>

// ---------------------------------------------------------------------------
// MiniGRUConv2d4 on GB300 (sm_103 PTX target -> legacy mma.sync path):
//   3x(conv3x3+BN[+sigmoid]) as one implicit GEMM using fp16
//   mma.sync.m16n8k16 (fp32 accum), BN folded into fp16 weights.
//   Then 4 directional affine scans with fused s-weighted combine.
// Shapes: B=4, Cin=64, C4=256, H=W=256. GEMM M=768, K=576, N=65536/batch.
// ---------------------------------------------------------------------------

#define B_  4
#define CIN 64
#define C4  256

static __device__ float g_zhs[(size_t)3 * B_ * C4 * 256 * 256]; // z/h/s planes
static __device__ __align__(16) __half gWtH[768 * 576];         // folded fp16 W
static __device__ float gBias[768];

struct ConvParams {
    const float* w[3];
    const float* g[3];
    const float* b[3];
    const float* m[3];
    const float* v[3];
};

// ---------------- fast sigmoid (no MUFU) ------------------------------------
__device__ __forceinline__ float fast_sigmoid(float x)
{
    float u = -1.44269504f * x;
    u = fminf(fmaxf(u, -60.f), 60.f);
    float fi = rintf(u);
    float f  = u - fi;
    float p = 1.54035304e-4f;
    p = fmaf(p, f, 1.33335581e-3f);
    p = fmaf(p, f, 9.61812910e-3f);
    p = fmaf(p, f, 5.55041087e-2f);
    p = fmaf(p, f, 2.40226507e-1f);
    p = fmaf(p, f, 6.93147181e-1f);
    p = fmaf(p, f, 1.0f);
    int ei = (int)fi;
    float e = __int_as_float(__float_as_int(p) + (ei << 23));
    float d = 1.0f + e;
    float r = __int_as_float(0x7EF311C3 - __float_as_int(d));
    r = r * (2.0f - d * r);
    r = r * (2.0f - d * r);
    r = r * (2.0f - d * r);
    return r;
}

// ---------------------------------------------------------------------------
// Prep: fold BN into fp16 weights, k = r*64+ci ordering; fp32 bias.
// ---------------------------------------------------------------------------
__global__ void prep_kernel(ConvParams P)
{
    int idx = blockIdx.x * 256 + threadIdx.x;
    if (idx < 768) {
        int set = idx >> 8, co = idx & 255;
        float inv = P.g[set][co] * rsqrtf(P.v[set][co] + 1e-5f);
        gBias[idx] = P.b[set][co] - P.m[set][co] * inv;
    }
    if (idx < 768 * 576) {
        int co_g = idx / 576;
        int k    = idx - co_g * 576;
        int r    = k >> 6;
        int ci   = k & 63;
        int set  = co_g >> 8;
        int co   = co_g & 255;
        float inv = P.g[set][co] * rsqrtf(P.v[set][co] + 1e-5f);
        gWtH[idx] = __float2half_rn(P.w[set][(co * 64 + ci) * 9 + r] * inv);
    }
}

// ---------------------------------------------------------------------------
// fp16 implicit-GEMM conv, mma.sync.m16n8k16.
// Block: 128 co x 128 px, BK=32 (16 half2), 256 threads (8 warps 4x2; each
// warp 32co x 64px). Double-buffered XOR-swizzled smem (conflict-free loads
// AND stores, verified per-lane).
// ---------------------------------------------------------------------------
__device__ __forceinline__ int swp(int n, int kp)
{
    return n * 16 + (kp ^ ((n & 7) << 1) ^ ((n >> 3) & 3));
}

__global__ __launch_bounds__(256, 2)
void conv_mma_kernel(const float* __restrict__ xs)
{
    __shared__ uint32_t As[2][2048];   // [co 0..127][kp 0..15] half2, swizzled
    __shared__ uint32_t Bs[2][2048];   // [n  0..127][kp 0..15] half2, swizzled

    const int tid = threadIdx.x;
    const int l   = tid & 31;
    const int w   = tid >> 5;
    const int wm  = w >> 1;            // 0..3
    const int wn  = w & 1;             // 0..1

    const int ntile = blockIdx.x;      // 0..511
    const int m0    = blockIdx.y << 7; // 0..640
    const int b     = blockIdx.z;
    const int y0    = ntile >> 1;
    const int x0    = (ntile & 1) << 7;

    const uint32_t* gW32 = (const uint32_t*)gWtH;

    uint32_t aR[8], bR[8];

    auto loadA = [&](int kt) {
#pragma unroll
        for (int i = 0; i < 8; ++i) {
            int e  = tid + (i << 8);
            int kp = e & 15, co = e >> 4;
            aR[i] = gW32[(size_t)(m0 + co) * 288 + kt * 16 + kp];
        }
    };
    auto loadB = [&](int kt) {
        const int r   = kt >> 1;
        const int r3  = r / 3;
        const int dy  = r3 - 1, dx = r - r3 * 3 - 1;
        const int row = y0 + dy;
        const bool rok = (unsigned)row < 256u;
        const int cib = (kt & 1) << 5;
#pragma unroll
        for (int i = 0; i < 8; ++i) {
            int e  = tid + (i << 8);
            int kp = e >> 7, n = e & 127;
            int ci0 = cib + (kp << 1);
            int xx  = x0 + n + dx;
            bool ok = rok && (unsigned)xx < 256u;
            float f0 = 0.f, f1 = 0.f;
            if (ok) {
                const float* p = xs + (((size_t)(b * CIN + ci0)) << 16)
                               + (row << 8) + xx;
                f0 = __ldg(p);
                f1 = __ldg(p + (1 << 16));
            }
            __half2 h2 = __floats2half2_rn(f0, f1);
            bR[i] = *(uint32_t*)&h2;
        }
    };
    auto stage = [&](int buf) {
#pragma unroll
        for (int i = 0; i < 8; ++i) {
            int e = tid + (i << 8);
            As[buf][swp(e >> 4, e & 15)] = aR[i];
            Bs[buf][swp(e & 127, e >> 7)] = bR[i];
        }
    };

    float acc[2][8][4];
#pragma unroll
    for (int mt = 0; mt < 2; ++mt)
#pragma unroll
        for (int nt = 0; nt < 8; ++nt)
#pragma unroll
            for (int c = 0; c < 4; ++c) acc[mt][nt][c] = 0.f;

    loadA(0); loadB(0); stage(0);
    __syncthreads();

    int cur = 0;
    for (int kt = 0; kt < 18; ++kt) {
        if (kt < 17) { loadA(kt + 1); loadB(kt + 1); }

#pragma unroll
        for (int ks = 0; ks < 2; ++ks) {
            const int kp0 = (ks << 3) + (l & 3);
            uint32_t a[2][4];
#pragma unroll
            for (int mt = 0; mt < 2; ++mt) {
                int mb = (wm << 5) + (mt << 4) + (l >> 2);
                a[mt][0] = As[cur][swp(mb, kp0)];
                a[mt][1] = As[cur][swp(mb + 8, kp0)];
                a[mt][2] = As[cur][swp(mb, kp0 + 4)];
                a[mt][3] = As[cur][swp(mb + 8, kp0 + 4)];
            }
#pragma unroll
            for (int nt = 0; nt < 8; ++nt) {
                int nb = (wn << 6) + (nt << 3) + (l >> 2);
                uint32_t b0 = Bs[cur][swp(nb, kp0)];
                uint32_t b1 = Bs[cur][swp(nb, kp0 + 4)];
#pragma unroll
                for (int mt = 0; mt < 2; ++mt) {
                    asm volatile(
                        "mma.sync.aligned.m16n8k16.row.col.f32.f16.f16.f32 "
                        "{%0,%1,%2,%3}, {%4,%5,%6,%7}, {%8,%9}, {%0,%1,%2,%3};"
                        : "+f"(acc[mt][nt][0]), "+f"(acc[mt][nt][1]),
                          "+f"(acc[mt][nt][2]), "+f"(acc[mt][nt][3])
                        : "r"(a[mt][0]), "r"(a[mt][1]),
                          "r"(a[mt][2]), "r"(a[mt][3]),
                          "r"(b0), "r"(b1));
                }
            }
        }
        __syncthreads();
        if (kt < 17) stage(cur ^ 1);
        __syncthreads();
        cur ^= 1;
    }

    // epilogue: + bias, sigmoid for sets 0/2, float2 stores to scratch planes
    const int set = m0 >> 8;
#pragma unroll
    for (int mt = 0; mt < 2; ++mt) {
#pragma unroll
        for (int rr = 0; rr < 2; ++rr) {
            int co_g = m0 + (wm << 5) + (mt << 4) + (l >> 2) + rr * 8;
            float bias = gBias[co_g];
            int ch = co_g & 255;
            size_t base = ((((size_t)set * B_ + b) * C4 + ch) << 16)
                        + ((size_t)y0 << 8);
#pragma unroll
            for (int nt = 0; nt < 8; ++nt) {
                int xx = x0 + (wn << 6) + (nt << 3) + ((l & 3) << 1);
                float v0 = acc[mt][nt][rr * 2 + 0] + bias;
                float v1 = acc[mt][nt][rr * 2 + 1] + bias;
                if (set != 1) { v0 = fast_sigmoid(v0); v1 = fast_sigmoid(v1); }
                *(float2*)&g_zhs[base + xx] = make_float2(v0, v1);
            }
        }
    }
}

// ---------------------------------------------------------------------------
// Vertical scans (groups 0 fwd / 1 bwd along H), fused s-weighted combine.
// ---------------------------------------------------------------------------
__global__ void scan_v_kernel(const float* __restrict__ h20,
                              const float* __restrict__ h21,
                              float* __restrict__ out)
{
    int t = blockIdx.x * 256 + threadIdx.x;
    int x = t & 255;
    int c = (t >> 8) & 63;
    int b = t >> 14;

    size_t zb = ((((size_t)0 * B_ + b) * C4 + c) << 16) + x;
    size_t hb = ((((size_t)1 * B_ + b) * C4 + c) << 16) + x;
    size_t sb = ((((size_t)2 * B_ + b) * C4 + c) << 16) + x;
    size_t ob = (((size_t)b * 64 + c) << 16) + x;

    float carry = h20[c];
    for (int y = 0; y < 256; ++y) {
        size_t off = (size_t)y << 8;
        float z  = g_zhs[zb + off];
        float hv = g_zhs[hb + off];
        float s  = g_zhs[sb + off];
        carry = z * hv + (1.f - z) * carry;
        out[ob + off] = s * carry;
    }
    const size_t coff = (size_t)64 << 16;
    zb += coff; hb += coff; sb += coff;
    carry = h21[c];
    for (int y = 255; y >= 0; --y) {
        size_t off = (size_t)y << 8;
        float z  = g_zhs[zb + off];
        float hv = g_zhs[hb + off];
        float s  = g_zhs[sb + off];
        carry = z * hv + (1.f - z) * carry;
        out[ob + off] += s * carry;
    }
}

// ---------------------------------------------------------------------------
// Horizontal scans (groups 2 fwd / 3 bwd along W): warp-shuffle affine scan.
// Composition: F_i = f_i o F_{i-1}; (a,b) o (pa,pb) = (a*pa, a*pb + b).
// ---------------------------------------------------------------------------
__device__ __forceinline__ void warp_affine_scan(float& a, float& b, int lane)
{
#pragma unroll
    for (int off = 1; off < 32; off <<= 1) {
        float pa = __shfl_up_sync(0xFFFFFFFFu, a, off);
        float pb = __shfl_up_sync(0xFFFFFFFFu, b, off);
        if (lane >= off) {
            b = fmaf(a, pb, b);
            a = a * pa;
        }
    }
}

__global__ void scan_h_kernel(const float* __restrict__ h30,
                              const float* __restrict__ h31,
                              float* __restrict__ out)
{
    int blk = blockIdx.x;
    int y = blk & 255;
    int c = (blk >> 8) & 63;
    int b = blk >> 14;
    int t = threadIdx.x;
    int warp = t >> 5;
    int lane = t & 31;

    __shared__ float wa[8], wb[8];
    __shared__ float rbuf[256];

    const size_t rowbase = (size_t)y << 8;
    auto idx = [&](int set, int ch, int col) {
        return ((((size_t)set * B_ + b) * C4 + ch) << 16) + rowbase + col;
    };

    // ---- group 2: forward, sequence position = t, col = t ----
    float a, bb;
    {
        float z  = g_zhs[idx(0, 128 + c, t)];
        float hv = g_zhs[idx(1, 128 + c, t)];
        a  = 1.f - z;
        bb = z * hv;
    }
    float s2 = g_zhs[idx(2, 128 + c, t)];
    warp_affine_scan(a, bb, lane);
    if (lane == 31) { wa[warp] = a; wb[warp] = bb; }
    __syncthreads();
    if (warp == 0 && lane < 8) {
        float xa = wa[lane], xb = wb[lane];
#pragma unroll
        for (int off = 1; off < 8; off <<= 1) {
            float pa = __shfl_up_sync(0xFFu, xa, off);
            float pb = __shfl_up_sync(0xFFu, xb, off);
            if (lane >= off) { xb = fmaf(xa, pb, xb); xa = xa * pa; }
        }
        wa[lane] = xa; wb[lane] = xb;
    }
    __syncthreads();
    float accv;
    {
        float Pa = 1.f, Pb = 0.f;
        if (warp > 0) { Pa = wa[warp - 1]; Pb = wb[warp - 1]; }
        float af = a * Pa;
        float bf = fmaf(a, Pb, bb);
        accv = s2 * fmaf(af, h30[c], bf);        // value for col t
    }
    __syncthreads();

    // ---- group 3: reverse, sequence position = t, col = 255 - t ----
    const int col = 255 - t;
    {
        float z  = g_zhs[idx(0, 192 + c, col)];
        float hv = g_zhs[idx(1, 192 + c, col)];
        a  = 1.f - z;
        bb = z * hv;
    }
    float s3 = g_zhs[idx(2, 192 + c, col)];
    warp_affine_scan(a, bb, lane);
    if (lane == 31) { wa[warp] = a; wb[warp] = bb; }
    __syncthreads();
    if (warp == 0 && lane < 8) {
        float xa = wa[lane], xb = wb[lane];
#pragma unroll
        for (int off = 1; off < 8; off <<= 1) {
            float pa = __shfl_up_sync(0xFFu, xa, off);
            float pb = __shfl_up_sync(0xFFu, xb, off);
            if (lane >= off) { xb = fmaf(xa, pb, xb); xa = xa * pa; }
        }
        wa[lane] = xa; wb[lane] = xb;
    }
    __syncthreads();
    {
        float Pa = 1.f, Pb = 0.f;
        if (warp > 0) { Pa = wa[warp - 1]; Pb = wb[warp - 1]; }
        float af = a * Pa;
        float bf = fmaf(a, Pb, bb);
        rbuf[col] = s3 * fmaf(af, h31[c], bf);   // value for col (255 - t)
    }
    __syncthreads();

    size_t o = (((size_t)b * 64 + c) << 16) + rowbase + t;
    out[o] += accv + rbuf[t];
}

// ---------------------------------------------------------------------------
extern "C" void kernel_launch(void* const* d_in, const int* in_sizes, int n_in,
                              void* d_out, int out_size)
{
    const float* xs = (const float*)d_in[0];

    ConvParams P;
    for (int s = 0; s < 3; ++s) {
        int base = 1 + s * 5;
        P.w[s] = (const float*)d_in[base + 0];
        P.g[s] = (const float*)d_in[base + 1];
        P.b[s] = (const float*)d_in[base + 2];
        P.m[s] = (const float*)d_in[base + 3];
        P.v[s] = (const float*)d_in[base + 4];
    }
    const float* h20 = (const float*)d_in[16];
    const float* h21 = (const float*)d_in[17];
    const float* h30 = (const float*)d_in[18];
    const float* h31 = (const float*)d_in[19];

    float* out = (float*)d_out;

    prep_kernel<<<1728, 256>>>(P);

    dim3 cgrid(512, 6, 4);
    conv_mma_kernel<<<cgrid, 256>>>(xs);

    scan_v_kernel<<<256, 256>>>(h20, h21, out);
    scan_h_kernel<<<65536, 256>>>(h30, h31, out);
}

// round 5
// speedup vs baseline: 5.1597x; 1.8701x over previous
#include <cuda_runtime.h>
#include <cuda_fp16.h>
#include <math.h>
#include <stdint.h>

// ---------------------------------------------------------------------------
// MiniGRUConv2d4 on GB300 (compute_103 PTX target -> legacy mma.sync path):
//   pass 1: transpose xs -> xh[b][y][x][ci] fp16
//   pass 2: 3x(conv3x3+BN[+sigmoid]) as implicit GEMM, fp16 mma.sync.m16n8k16,
//           activations cp.async'd once per CTA (full-row halo tile),
//           weights streamed via 4-deep cp.async ring.
//   pass 3/4: directional affine scans with fused s-weighted combine.
// ---------------------------------------------------------------------------

#define B_  4
#define CIN 64
#define C4  256

static __device__ float g_zhs[(size_t)3 * B_ * C4 * 256 * 256];     // z/h/s planes
static __device__ __align__(16) __half gXh[(size_t)B_ * 256 * 256 * 64];
static __device__ __align__(16) __half gWtH[768 * 576];
static __device__ float gBias[768];

struct ConvParams {
    const float* w[3];
    const float* g[3];
    const float* b[3];
    const float* m[3];
    const float* v[3];
};

// ---------------- fast sigmoid (no MUFU) ------------------------------------
__device__ __forceinline__ float fast_sigmoid(float x)
{
    float u = -1.44269504f * x;
    u = fminf(fmaxf(u, -60.f), 60.f);
    float fi = rintf(u);
    float f  = u - fi;
    float p = 1.54035304e-4f;
    p = fmaf(p, f, 1.33335581e-3f);
    p = fmaf(p, f, 9.61812910e-3f);
    p = fmaf(p, f, 5.55041087e-2f);
    p = fmaf(p, f, 2.40226507e-1f);
    p = fmaf(p, f, 6.93147181e-1f);
    p = fmaf(p, f, 1.0f);
    int ei = (int)fi;
    float e = __int_as_float(__float_as_int(p) + (ei << 23));
    float d = 1.0f + e;
    float r = __int_as_float(0x7EF311C3 - __float_as_int(d));
    r = r * (2.0f - d * r);
    r = r * (2.0f - d * r);
    r = r * (2.0f - d * r);
    return r;
}

// ---------------- small helpers ---------------------------------------------
__device__ __forceinline__ uint32_t smem_u32(const void* p)
{
    uint32_t a;
    asm("{ .reg .u64 t; cvta.to.shared.u64 t, %1; cvt.u32.u64 %0, t; }"
        : "=r"(a) : "l"(p));
    return a;
}
__device__ __forceinline__ void cp16(uint32_t dst, const void* src)
{
    size_t g = __cvta_generic_to_global(src);
    asm volatile("cp.async.cg.shared.global [%0], [%1], 16;"
                 :: "r"(dst), "l"(g) : "memory");
}
__device__ __forceinline__ uint32_t lds32(uint32_t a)
{
    uint32_t v;
    asm volatile("ld.shared.b32 %0, [%1];" : "=r"(v) : "r"(a));
    return v;
}
__device__ __forceinline__ void sts_zero16(uint32_t a)
{
    asm volatile("st.shared.v4.u32 [%0], {%1,%1,%1,%1};" :: "r"(a), "r"(0u) : "memory");
}

// ---------------------------------------------------------------------------
// Prep: fold BN into fp16 weights, k = r*64+ci ordering; fp32 bias.
// ---------------------------------------------------------------------------
__global__ void prep_kernel(ConvParams P)
{
    int idx = blockIdx.x * 256 + threadIdx.x;
    if (idx < 768) {
        int set = idx >> 8, co = idx & 255;
        float inv = P.g[set][co] * rsqrtf(P.v[set][co] + 1e-5f);
        gBias[idx] = P.b[set][co] - P.m[set][co] * inv;
    }
    if (idx < 768 * 576) {
        int co_g = idx / 576;
        int k    = idx - co_g * 576;
        int r    = k >> 6;
        int ci   = k & 63;
        int set  = co_g >> 8;
        int co   = co_g & 255;
        float inv = P.g[set][co] * rsqrtf(P.v[set][co] + 1e-5f);
        gWtH[idx] = __float2half_rn(P.w[set][(co * 64 + ci) * 9 + r] * inv);
    }
}

// ---------------------------------------------------------------------------
// Transpose xs [b][ci][y][x] fp32 -> gXh [b][y][x][ci] fp16.
// Block handles (b, y, 128-x tile). 256 threads.
// ---------------------------------------------------------------------------
__global__ __launch_bounds__(256)
void xpose_kernel(const float* __restrict__ xs)
{
    __shared__ float S[64][129];
    const int xt = blockIdx.x;      // 0..1
    const int y  = blockIdx.y;      // 0..255
    const int b  = blockIdx.z;      // 0..3
    const int tid = threadIdx.x;

    const float* src = xs + (((size_t)b * CIN) << 16) + (y << 8) + xt * 128;
#pragma unroll
    for (int p = 0; p < 8; ++p) {
        int idx = tid + (p << 8);
        int ci  = idx >> 5;          // 0..63
        int x4  = idx & 31;          // 0..31
        float4 v = *(const float4*)(src + (((size_t)ci) << 16) + (x4 << 2));
        S[ci][x4 * 4 + 0] = v.x;
        S[ci][x4 * 4 + 1] = v.y;
        S[ci][x4 * 4 + 2] = v.z;
        S[ci][x4 * 4 + 3] = v.w;
    }
    __syncthreads();

    __half* dst = gXh + ((((size_t)b * 256 + y) * 256) + xt * 128) * 64;
#pragma unroll
    for (int p = 0; p < 4; ++p) {
        int chunk = tid + (p << 8);
        int g = chunk & 7;
        int x = chunk >> 3;          // 0..127
        int c0 = g * 8;
        __half2 h0 = __floats2half2_rn(S[c0 + 0][x], S[c0 + 1][x]);
        __half2 h1 = __floats2half2_rn(S[c0 + 2][x], S[c0 + 3][x]);
        __half2 h2 = __floats2half2_rn(S[c0 + 4][x], S[c0 + 5][x]);
        __half2 h3 = __floats2half2_rn(S[c0 + 6][x], S[c0 + 7][x]);
        uint4 val;
        val.x = *(uint32_t*)&h0; val.y = *(uint32_t*)&h1;
        val.z = *(uint32_t*)&h2; val.w = *(uint32_t*)&h3;
        *(uint4*)(dst + (size_t)x * 64 + g * 8) = val;
    }
}

// ---------------------------------------------------------------------------
// Conv: CTA = full row (256 px) x 128 couts. 8 warps (2m x 4n), warp 64x64.
// B halo tile [3 rows][258 slots][64 ci] fp16, swizzled 16B groups, cp.async
// once. A (weights) 4-deep cp.async ring, 1 syncthreads per k32 step.
// ---------------------------------------------------------------------------
#define BT_BYTES (3 * 260 * 128)                 // 99840
#define A_BUF    16384
#define SMEM_BYTES (BT_BYTES + 4 * A_BUF)        // 165376

__global__ __launch_bounds__(256)
void conv_mma_kernel()
{
    extern __shared__ char smem[];
    const uint32_t sB = smem_u32(smem);
    const uint32_t sA = sB + BT_BYTES;

    const int tid = threadIdx.x;
    const int l   = tid & 31;
    const int w   = tid >> 5;
    const int wm  = w >> 2;            // 0..1
    const int wn  = w & 3;             // 0..3

    const int y0 = blockIdx.x;         // 0..255
    const int m0 = blockIdx.y << 7;    // 0..640
    const int b  = blockIdx.z;

    // ---- fill B halo tile (cp.async / zero-fill), part of group 0 ----
    for (int t = tid; t < 6192; t += 256) {
        int row  = t / 2064;                   // 0..2
        int rem  = t - row * 2064;
        int slot = rem >> 3;                   // 0..257
        int g    = rem & 7;
        int y    = y0 - 1 + row;
        int x    = slot - 1;
        uint32_t dst = sB + (uint32_t)(row * 260 + slot) * 128
                     + (uint32_t)((g ^ (slot & 7)) << 4);
        if ((unsigned)y < 256u && (unsigned)x < 256u)
            cp16(dst, gXh + ((((size_t)b * 256 + y) * 256 + x) * 64 + g * 8));
        else
            sts_zero16(dst);
    }

    // ---- A ring producer ----
    auto issueA = [&](int kt2) {
        if (kt2 < 18) {
            uint32_t base = sA + (uint32_t)((kt2 & 3) * A_BUF);
            const __half* src = gWtH + (size_t)m0 * 576 + kt2 * 32;
#pragma unroll
            for (int p = 0; p < 4; ++p) {
                int chunk = tid + (p << 8);
                int co  = chunk >> 2;          // 0..255
                int kpg = chunk & 3;
                uint32_t wrd = (uint32_t)(co << 4)
                             + (uint32_t)((kpg ^ ((co >> 1) & 3)) << 2);
                cp16(base + (wrd << 2), src + (size_t)co * 576 + (kpg << 3));
            }
        }
        asm volatile("cp.async.commit_group;" ::: "memory");
    };

    issueA(0);   // group0 = B tile + A chunk 0
    issueA(1);
    issueA(2);

    float acc[4][8][4];
#pragma unroll
    for (int mt = 0; mt < 4; ++mt)
#pragma unroll
        for (int nt = 0; nt < 8; ++nt)
#pragma unroll
            for (int c = 0; c < 4; ++c) acc[mt][nt][c] = 0.f;

    for (int kt = 0; kt < 18; ++kt) {
        asm volatile("cp.async.wait_group 2;" ::: "memory");
        __syncthreads();

        const uint32_t abuf = sA + (uint32_t)((kt & 3) * A_BUF);
        const int r   = kt >> 1;
        const int row = r / 3;                 // 0..2 (dy+1)
        const int dxp = r - row * 3;           // 0..2 (dx+1)
        const uint32_t rowbase = sB + (uint32_t)(row * 260) * 128;

#pragma unroll
        for (int ks = 0; ks < 2; ++ks) {
            const int kpl = (ks << 3) + (l & 3);
            uint32_t a[4][4];
#pragma unroll
            for (int mt = 0; mt < 4; ++mt) {
                int c0 = (wm << 6) + (mt << 4) + (l >> 2);
                int c1 = c0 + 8;
                uint32_t w00 = (uint32_t)(c0 << 4)
                             + (uint32_t)((((kpl >> 2) ^ ((c0 >> 1) & 3)) << 2) + (kpl & 3));
                uint32_t w01 = (uint32_t)(c1 << 4)
                             + (uint32_t)((((kpl >> 2) ^ ((c1 >> 1) & 3)) << 2) + (kpl & 3));
                int kph = kpl + 4;
                uint32_t w10 = (uint32_t)(c0 << 4)
                             + (uint32_t)((((kph >> 2) ^ ((c0 >> 1) & 3)) << 2) + (kph & 3));
                uint32_t w11 = (uint32_t)(c1 << 4)
                             + (uint32_t)((((kph >> 2) ^ ((c1 >> 1) & 3)) << 2) + (kph & 3));
                a[mt][0] = lds32(abuf + (w00 << 2));
                a[mt][1] = lds32(abuf + (w01 << 2));
                a[mt][2] = lds32(abuf + (w10 << 2));
                a[mt][3] = lds32(abuf + (w11 << 2));
            }

            const int ga = ((kt & 1) << 2) + (ks << 1);
#pragma unroll
            for (int nt = 0; nt < 8; ++nt) {
                int slot = (wn << 6) + (nt << 3) + (l >> 2) + dxp;
                uint32_t sb8 = rowbase + (uint32_t)slot * 128;
                uint32_t b0 = lds32(sb8 + (uint32_t)((((ga    ) ^ (slot & 7)) << 2) + (l & 3)) * 4);
                uint32_t b1 = lds32(sb8 + (uint32_t)((((ga + 1) ^ (slot & 7)) << 2) + (l & 3)) * 4);
#pragma unroll
                for (int mt = 0; mt < 4; ++mt) {
                    asm volatile(
                        "mma.sync.aligned.m16n8k16.row.col.f32.f16.f16.f32 "
                        "{%0,%1,%2,%3}, {%4,%5,%6,%7}, {%8,%9}, {%0,%1,%2,%3};"
                        : "+f"(acc[mt][nt][0]), "+f"(acc[mt][nt][1]),
                          "+f"(acc[mt][nt][2]), "+f"(acc[mt][nt][3])
                        : "r"(a[mt][0]), "r"(a[mt][1]),
                          "r"(a[mt][2]), "r"(a[mt][3]),
                          "r"(b0), "r"(b1));
                }
            }
        }
        issueA(kt + 3);
    }

    // ---- epilogue: bias (+sigmoid), float2 stores ----
    const int set = m0 >> 8;
    const int chb = m0 & 255;
#pragma unroll
    for (int mt = 0; mt < 4; ++mt) {
#pragma unroll
        for (int rr = 0; rr < 2; ++rr) {
            int cloc = (wm << 6) + (mt << 4) + (l >> 2) + (rr << 3);
            float bias = gBias[m0 + cloc];
            int ch = chb + cloc;
            size_t base = ((((size_t)set * B_ + b) * C4 + ch) << 16)
                        + ((size_t)y0 << 8);
#pragma unroll
            for (int nt = 0; nt < 8; ++nt) {
                int n = (wn << 6) + (nt << 3) + ((l & 3) << 1);
                float v0 = acc[mt][nt][rr * 2 + 0] + bias;
                float v1 = acc[mt][nt][rr * 2 + 1] + bias;
                if (set != 1) { v0 = fast_sigmoid(v0); v1 = fast_sigmoid(v1); }
                *(float2*)&g_zhs[base + n] = make_float2(v0, v1);
            }
        }
    }
}

// ---------------------------------------------------------------------------
// Vertical scans (groups 0 fwd / 1 bwd along H), fused s-weighted combine.
// ---------------------------------------------------------------------------
__global__ void scan_v_kernel(const float* __restrict__ h20,
                              const float* __restrict__ h21,
                              float* __restrict__ out)
{
    int t = blockIdx.x * 256 + threadIdx.x;
    int x = t & 255;
    int c = (t >> 8) & 63;
    int b = t >> 14;

    size_t zb = ((((size_t)0 * B_ + b) * C4 + c) << 16) + x;
    size_t hb = ((((size_t)1 * B_ + b) * C4 + c) << 16) + x;
    size_t sb = ((((size_t)2 * B_ + b) * C4 + c) << 16) + x;
    size_t ob = (((size_t)b * 64 + c) << 16) + x;

    float carry = h20[c];
    for (int y = 0; y < 256; ++y) {
        size_t off = (size_t)y << 8;
        float z  = g_zhs[zb + off];
        float hv = g_zhs[hb + off];
        float s  = g_zhs[sb + off];
        carry = z * hv + (1.f - z) * carry;
        out[ob + off] = s * carry;
    }
    const size_t coff = (size_t)64 << 16;
    zb += coff; hb += coff; sb += coff;
    carry = h21[c];
    for (int y = 255; y >= 0; --y) {
        size_t off = (size_t)y << 8;
        float z  = g_zhs[zb + off];
        float hv = g_zhs[hb + off];
        float s  = g_zhs[sb + off];
        carry = z * hv + (1.f - z) * carry;
        out[ob + off] += s * carry;
    }
}

// ---------------------------------------------------------------------------
// Horizontal scans (groups 2 fwd / 3 bwd along W): warp-shuffle affine scan.
// ---------------------------------------------------------------------------
__device__ __forceinline__ void warp_affine_scan(float& a, float& b, int lane)
{
#pragma unroll
    for (int off = 1; off < 32; off <<= 1) {
        float pa = __shfl_up_sync(0xFFFFFFFFu, a, off);
        float pb = __shfl_up_sync(0xFFFFFFFFu, b, off);
        if (lane >= off) {
            b = fmaf(a, pb, b);
            a = a * pa;
        }
    }
}

__global__ void scan_h_kernel(const float* __restrict__ h30,
                              const float* __restrict__ h31,
                              float* __restrict__ out)
{
    int blk = blockIdx.x;
    int y = blk & 255;
    int c = (blk >> 8) & 63;
    int b = blk >> 14;
    int t = threadIdx.x;
    int warp = t >> 5;
    int lane = t & 31;

    __shared__ float wa[8], wb[8];
    __shared__ float rbuf[256];

    const size_t rowbase = (size_t)y << 8;
    auto idx = [&](int set, int ch, int col) {
        return ((((size_t)set * B_ + b) * C4 + ch) << 16) + rowbase + col;
    };

    float a, bb;
    {
        float z  = g_zhs[idx(0, 128 + c, t)];
        float hv = g_zhs[idx(1, 128 + c, t)];
        a  = 1.f - z;
        bb = z * hv;
    }
    float s2 = g_zhs[idx(2, 128 + c, t)];
    warp_affine_scan(a, bb, lane);
    if (lane == 31) { wa[warp] = a; wb[warp] = bb; }
    __syncthreads();
    if (warp == 0 && lane < 8) {
        float xa = wa[lane], xb = wb[lane];
#pragma unroll
        for (int off = 1; off < 8; off <<= 1) {
            float pa = __shfl_up_sync(0xFFu, xa, off);
            float pb = __shfl_up_sync(0xFFu, xb, off);
            if (lane >= off) { xb = fmaf(xa, pb, xb); xa = xa * pa; }
        }
        wa[lane] = xa; wb[lane] = xb;
    }
    __syncthreads();
    float accv;
    {
        float Pa = 1.f, Pb = 0.f;
        if (warp > 0) { Pa = wa[warp - 1]; Pb = wb[warp - 1]; }
        float af = a * Pa;
        float bf = fmaf(a, Pb, bb);
        accv = s2 * fmaf(af, h30[c], bf);
    }
    __syncthreads();

    const int col = 255 - t;
    {
        float z  = g_zhs[idx(0, 192 + c, col)];
        float hv = g_zhs[idx(1, 192 + c, col)];
        a  = 1.f - z;
        bb = z * hv;
    }
    float s3 = g_zhs[idx(2, 192 + c, col)];
    warp_affine_scan(a, bb, lane);
    if (lane == 31) { wa[warp] = a; wb[warp] = bb; }
    __syncthreads();
    if (warp == 0 && lane < 8) {
        float xa = wa[lane], xb = wb[lane];
#pragma unroll
        for (int off = 1; off < 8; off <<= 1) {
            float pa = __shfl_up_sync(0xFFu, xa, off);
            float pb = __shfl_up_sync(0xFFu, xb, off);
            if (lane >= off) { xb = fmaf(xa, pb, xb); xa = xa * pa; }
        }
        wa[lane] = xa; wb[lane] = xb;
    }
    __syncthreads();
    {
        float Pa = 1.f, Pb = 0.f;
        if (warp > 0) { Pa = wa[warp - 1]; Pb = wb[warp - 1]; }
        float af = a * Pa;
        float bf = fmaf(a, Pb, bb);
        rbuf[col] = s3 * fmaf(af, h31[c], bf);
    }
    __syncthreads();

    size_t o = (((size_t)b * 64 + c) << 16) + rowbase + t;
    out[o] += accv + rbuf[t];
}

// ---------------------------------------------------------------------------
extern "C" void kernel_launch(void* const* d_in, const int* in_sizes, int n_in,
                              void* d_out, int out_size)
{
    const float* xs = (const float*)d_in[0];

    ConvParams P;
    for (int s = 0; s < 3; ++s) {
        int base = 1 + s * 5;
        P.w[s] = (const float*)d_in[base + 0];
        P.g[s] = (const float*)d_in[base + 1];
        P.b[s] = (const float*)d_in[base + 2];
        P.m[s] = (const float*)d_in[base + 3];
        P.v[s] = (const float*)d_in[base + 4];
    }
    const float* h20 = (const float*)d_in[16];
    const float* h21 = (const float*)d_in[17];
    const float* h30 = (const float*)d_in[18];
    const float* h31 = (const float*)d_in[19];

    float* out = (float*)d_out;

    cudaFuncSetAttribute(conv_mma_kernel,
                         cudaFuncAttributeMaxDynamicSharedMemorySize, SMEM_BYTES);

    dim3 xgrid(2, 256, 4);
    xpose_kernel<<<xgrid, 256>>>(xs);

    prep_kernel<<<1728, 256>>>(P);

    dim3 cgrid(256, 6, 4);
    conv_mma_kernel<<<cgrid, 256, SMEM_BYTES>>>();

    scan_v_kernel<<<256, 256>>>(h20, h21, out);
    scan_h_kernel<<<65536, 256>>>(h30, h31, out);
}

// round 6
// speedup vs baseline: 6.3363x; 1.2280x over previous
#include <cuda_runtime.h>
#include <cuda_fp16.h>
#include <math.h>
#include <stdint.h>

// ---------------------------------------------------------------------------
// MiniGRUConv2d4 on GB300 (compute_103 PTX target -> legacy mma.sync path):
//   pass 1: transpose xs -> xh[b][y][x][ci] fp16
//   pass 2: 3x(conv3x3+BN[+sigmoid]) implicit GEMM, fp16 mma.sync.m16n8k16,
//           halo tile cp.async'd once per CTA, weights via cp.async ring,
//           2 CTAs/SM.
//   pass 3: vertical scans (y-unrolled, high MLP) + fused combine
//   pass 4: horizontal scans (warp-per-row, 8 elem/lane serial) + combine
// ---------------------------------------------------------------------------

#define B_  4
#define CIN 64
#define C4  256

static __device__ float g_zhs[(size_t)3 * B_ * C4 * 256 * 256];     // z/h/s planes
static __device__ __align__(16) __half gXh[(size_t)B_ * 256 * 256 * 64];
static __device__ __align__(16) __half gWtH[768 * 576];
static __device__ float gBias[768];

struct ConvParams {
    const float* w[3];
    const float* g[3];
    const float* b[3];
    const float* m[3];
    const float* v[3];
};

// ---------------- fast sigmoid (no MUFU) ------------------------------------
__device__ __forceinline__ float fast_sigmoid(float x)
{
    float u = -1.44269504f * x;
    u = fminf(fmaxf(u, -60.f), 60.f);
    float fi = rintf(u);
    float f  = u - fi;
    float p = 1.54035304e-4f;
    p = fmaf(p, f, 1.33335581e-3f);
    p = fmaf(p, f, 9.61812910e-3f);
    p = fmaf(p, f, 5.55041087e-2f);
    p = fmaf(p, f, 2.40226507e-1f);
    p = fmaf(p, f, 6.93147181e-1f);
    p = fmaf(p, f, 1.0f);
    int ei = (int)fi;
    float e = __int_as_float(__float_as_int(p) + (ei << 23));
    float d = 1.0f + e;
    float r = __int_as_float(0x7EF311C3 - __float_as_int(d));
    r = r * (2.0f - d * r);
    r = r * (2.0f - d * r);
    r = r * (2.0f - d * r);
    return r;
}

// ---------------- small helpers ---------------------------------------------
__device__ __forceinline__ uint32_t smem_u32(const void* p)
{
    uint32_t a;
    asm("{ .reg .u64 t; cvta.to.shared.u64 t, %1; cvt.u32.u64 %0, t; }"
        : "=r"(a) : "l"(p));
    return a;
}
__device__ __forceinline__ void cp16(uint32_t dst, const void* src)
{
    size_t g = __cvta_generic_to_global(src);
    asm volatile("cp.async.cg.shared.global [%0], [%1], 16;"
                 :: "r"(dst), "l"(g) : "memory");
}
__device__ __forceinline__ uint32_t lds32(uint32_t a)
{
    uint32_t v;
    asm volatile("ld.shared.b32 %0, [%1];" : "=r"(v) : "r"(a));
    return v;
}
__device__ __forceinline__ void sts_zero16(uint32_t a)
{
    asm volatile("st.shared.v4.u32 [%0], {%1,%1,%1,%1};" :: "r"(a), "r"(0u) : "memory");
}

// ---------------------------------------------------------------------------
// Prep: fold BN into fp16 weights, k = r*64+ci ordering; fp32 bias.
// ---------------------------------------------------------------------------
__global__ void prep_kernel(ConvParams P)
{
    int idx = blockIdx.x * 256 + threadIdx.x;
    if (idx < 768) {
        int set = idx >> 8, co = idx & 255;
        float inv = P.g[set][co] * rsqrtf(P.v[set][co] + 1e-5f);
        gBias[idx] = P.b[set][co] - P.m[set][co] * inv;
    }
    if (idx < 768 * 576) {
        int co_g = idx / 576;
        int k    = idx - co_g * 576;
        int r    = k >> 6;
        int ci   = k & 63;
        int set  = co_g >> 8;
        int co   = co_g & 255;
        float inv = P.g[set][co] * rsqrtf(P.v[set][co] + 1e-5f);
        gWtH[idx] = __float2half_rn(P.w[set][(co * 64 + ci) * 9 + r] * inv);
    }
}

// ---------------------------------------------------------------------------
// Transpose xs [b][ci][y][x] fp32 -> gXh [b][y][x][ci] fp16.
// ---------------------------------------------------------------------------
__global__ __launch_bounds__(256)
void xpose_kernel(const float* __restrict__ xs)
{
    __shared__ float S[64][129];
    const int xt = blockIdx.x;
    const int y  = blockIdx.y;
    const int b  = blockIdx.z;
    const int tid = threadIdx.x;

    const float* src = xs + (((size_t)b * CIN) << 16) + (y << 8) + xt * 128;
#pragma unroll
    for (int p = 0; p < 8; ++p) {
        int idx = tid + (p << 8);
        int ci  = idx >> 5;
        int x4  = idx & 31;
        float4 v = *(const float4*)(src + (((size_t)ci) << 16) + (x4 << 2));
        S[ci][x4 * 4 + 0] = v.x;
        S[ci][x4 * 4 + 1] = v.y;
        S[ci][x4 * 4 + 2] = v.z;
        S[ci][x4 * 4 + 3] = v.w;
    }
    __syncthreads();

    __half* dst = gXh + ((((size_t)b * 256 + y) * 256) + xt * 128) * 64;
#pragma unroll
    for (int p = 0; p < 4; ++p) {
        int chunk = tid + (p << 8);
        int g = chunk & 7;
        int x = chunk >> 3;
        int c0 = g * 8;
        __half2 h0 = __floats2half2_rn(S[c0 + 0][x], S[c0 + 1][x]);
        __half2 h1 = __floats2half2_rn(S[c0 + 2][x], S[c0 + 3][x]);
        __half2 h2 = __floats2half2_rn(S[c0 + 4][x], S[c0 + 5][x]);
        __half2 h3 = __floats2half2_rn(S[c0 + 6][x], S[c0 + 7][x]);
        uint4 val;
        val.x = *(uint32_t*)&h0; val.y = *(uint32_t*)&h1;
        val.z = *(uint32_t*)&h2; val.w = *(uint32_t*)&h3;
        *(uint4*)(dst + (size_t)x * 64 + g * 8) = val;
    }
}

// ---------------------------------------------------------------------------
// Conv: CTA = 128 px x 128 couts, 8 warps (4m x 2n), warp tile 32co x 64px.
// B halo [3 rows][130 slots][64 ci] fp16 swizzled, cp.async once.
// A (weights) 4-deep cp.async ring. 2 CTAs/SM.
// ---------------------------------------------------------------------------
#define BT_STRIDE 132
#define BT_BYTES  (3 * BT_STRIDE * 128)          // 50688
#define A_BUF     8192
#define SMEM_BYTES (BT_BYTES + 4 * A_BUF)        // 83456

__global__ __launch_bounds__(256, 2)
void conv_mma_kernel()
{
    extern __shared__ char smem[];
    const uint32_t sB = smem_u32(smem);
    const uint32_t sA = sB + BT_BYTES;

    const int tid = threadIdx.x;
    const int l   = tid & 31;
    const int w   = tid >> 5;
    const int wm  = w >> 1;            // 0..3 (32 co each)
    const int wn  = w & 1;             // 0..1 (64 px each)

    const int bx = blockIdx.x;         // 0..511
    const int y0 = bx >> 1;
    const int x0 = (bx & 1) << 7;
    const int m0 = blockIdx.y << 7;    // 0..640
    const int b  = blockIdx.z;

    // ---- fill B halo tile (cp.async / zero-fill), part of group 0 ----
    for (int t = tid; t < 3120; t += 256) {
        int row  = t / 1040;                   // 0..2
        int rem  = t - row * 1040;
        int slot = rem >> 3;                   // 0..129
        int g    = rem & 7;
        int y    = y0 - 1 + row;
        int x    = x0 + slot - 1;
        uint32_t dst = sB + (uint32_t)(row * BT_STRIDE + slot) * 128
                     + (uint32_t)((g ^ (slot & 7)) << 4);
        if ((unsigned)y < 256u && (unsigned)x < 256u)
            cp16(dst, gXh + ((((size_t)b * 256 + y) * 256 + x) * 64 + g * 8));
        else
            sts_zero16(dst);
    }

    // ---- A ring producer: 128co x 32k fp16 per chunk ----
    auto issueA = [&](int kt2) {
        if (kt2 < 18) {
            uint32_t base = sA + (uint32_t)((kt2 & 3) * A_BUF);
            const __half* src = gWtH + (size_t)m0 * 576 + kt2 * 32;
#pragma unroll
            for (int p = 0; p < 2; ++p) {
                int chunk = tid + (p << 8);
                int co  = chunk >> 2;          // 0..127
                int kpg = chunk & 3;
                uint32_t wrd = (uint32_t)(co << 4)
                             + (uint32_t)((kpg ^ ((co >> 1) & 3)) << 2);
                cp16(base + (wrd << 2), src + (size_t)co * 576 + (kpg << 3));
            }
        }
        asm volatile("cp.async.commit_group;" ::: "memory");
    };

    issueA(0);
    issueA(1);
    issueA(2);

    float acc[2][8][4];
#pragma unroll
    for (int mt = 0; mt < 2; ++mt)
#pragma unroll
        for (int nt = 0; nt < 8; ++nt)
#pragma unroll
            for (int c = 0; c < 4; ++c) acc[mt][nt][c] = 0.f;

    for (int kt = 0; kt < 18; ++kt) {
        asm volatile("cp.async.wait_group 2;" ::: "memory");
        __syncthreads();

        const uint32_t abuf = sA + (uint32_t)((kt & 3) * A_BUF);
        const int r   = kt >> 1;
        const int row = r / 3;
        const int dxp = r - row * 3;
        const uint32_t rowbase = sB + (uint32_t)(row * BT_STRIDE) * 128;

#pragma unroll
        for (int ks = 0; ks < 2; ++ks) {
            const int kpl = (ks << 3) + (l & 3);
            const int kph = kpl + 4;
            uint32_t a[2][4];
#pragma unroll
            for (int mt = 0; mt < 2; ++mt) {
                int c0 = (wm << 5) + (mt << 4) + (l >> 2);
                int c1 = c0 + 8;
                uint32_t w00 = (uint32_t)(c0 << 4)
                             + (uint32_t)((((kpl >> 2) ^ ((c0 >> 1) & 3)) << 2) + (kpl & 3));
                uint32_t w01 = (uint32_t)(c1 << 4)
                             + (uint32_t)((((kpl >> 2) ^ ((c1 >> 1) & 3)) << 2) + (kpl & 3));
                uint32_t w10 = (uint32_t)(c0 << 4)
                             + (uint32_t)((((kph >> 2) ^ ((c0 >> 1) & 3)) << 2) + (kph & 3));
                uint32_t w11 = (uint32_t)(c1 << 4)
                             + (uint32_t)((((kph >> 2) ^ ((c1 >> 1) & 3)) << 2) + (kph & 3));
                a[mt][0] = lds32(abuf + (w00 << 2));
                a[mt][1] = lds32(abuf + (w01 << 2));
                a[mt][2] = lds32(abuf + (w10 << 2));
                a[mt][3] = lds32(abuf + (w11 << 2));
            }

            const int ga = ((kt & 1) << 2) + (ks << 1);
#pragma unroll
            for (int nt = 0; nt < 8; ++nt) {
                int slot = (wn << 6) + (nt << 3) + (l >> 2) + dxp;
                uint32_t sb8 = rowbase + (uint32_t)slot * 128;
                uint32_t b0 = lds32(sb8 + (uint32_t)((((ga    ) ^ (slot & 7)) << 2) + (l & 3)) * 4);
                uint32_t b1 = lds32(sb8 + (uint32_t)((((ga + 1) ^ (slot & 7)) << 2) + (l & 3)) * 4);
#pragma unroll
                for (int mt = 0; mt < 2; ++mt) {
                    asm volatile(
                        "mma.sync.aligned.m16n8k16.row.col.f32.f16.f16.f32 "
                        "{%0,%1,%2,%3}, {%4,%5,%6,%7}, {%8,%9}, {%0,%1,%2,%3};"
                        : "+f"(acc[mt][nt][0]), "+f"(acc[mt][nt][1]),
                          "+f"(acc[mt][nt][2]), "+f"(acc[mt][nt][3])
                        : "r"(a[mt][0]), "r"(a[mt][1]),
                          "r"(a[mt][2]), "r"(a[mt][3]),
                          "r"(b0), "r"(b1));
                }
            }
        }
        issueA(kt + 3);
    }

    // ---- epilogue: bias (+sigmoid), float2 stores ----
    const int set = m0 >> 8;
    const int chb = m0 & 255;
#pragma unroll
    for (int mt = 0; mt < 2; ++mt) {
#pragma unroll
        for (int rr = 0; rr < 2; ++rr) {
            int cloc = (wm << 5) + (mt << 4) + (l >> 2) + (rr << 3);
            float bias = gBias[m0 + cloc];
            int ch = chb + cloc;
            size_t base = ((((size_t)set * B_ + b) * C4 + ch) << 16)
                        + ((size_t)y0 << 8) + x0;
#pragma unroll
            for (int nt = 0; nt < 8; ++nt) {
                int n = (wn << 6) + (nt << 3) + ((l & 3) << 1);
                float v0 = acc[mt][nt][rr * 2 + 0] + bias;
                float v1 = acc[mt][nt][rr * 2 + 1] + bias;
                if (set != 1) { v0 = fast_sigmoid(v0); v1 = fast_sigmoid(v1); }
                *(float2*)&g_zhs[base + n] = make_float2(v0, v1);
            }
        }
    }
}

// ---------------------------------------------------------------------------
// Vertical scans, y-unrolled x4 for MLP. Fused s-weighted combine.
// ---------------------------------------------------------------------------
__global__ void scan_v_kernel(const float* __restrict__ h20,
                              const float* __restrict__ h21,
                              float* __restrict__ out)
{
    int t = blockIdx.x * 256 + threadIdx.x;
    int x = t & 255;
    int c = (t >> 8) & 63;
    int b = t >> 14;

    size_t zb = ((((size_t)0 * B_ + b) * C4 + c) << 16) + x;
    size_t hb = ((((size_t)1 * B_ + b) * C4 + c) << 16) + x;
    size_t sb = ((((size_t)2 * B_ + b) * C4 + c) << 16) + x;
    size_t ob = (((size_t)b * 64 + c) << 16) + x;

    float carry = h20[c];
    for (int y = 0; y < 256; y += 4) {
        float z0, z1, z2, z3, q0, q1, q2, q3, s0, s1, s2, s3;
        size_t o0 = (size_t)y << 8, o1 = o0 + 256, o2 = o0 + 512, o3 = o0 + 768;
        z0 = g_zhs[zb + o0]; z1 = g_zhs[zb + o1]; z2 = g_zhs[zb + o2]; z3 = g_zhs[zb + o3];
        q0 = g_zhs[hb + o0]; q1 = g_zhs[hb + o1]; q2 = g_zhs[hb + o2]; q3 = g_zhs[hb + o3];
        s0 = g_zhs[sb + o0]; s1 = g_zhs[sb + o1]; s2 = g_zhs[sb + o2]; s3 = g_zhs[sb + o3];
        carry = z0 * q0 + (1.f - z0) * carry; out[ob + o0] = s0 * carry;
        carry = z1 * q1 + (1.f - z1) * carry; out[ob + o1] = s1 * carry;
        carry = z2 * q2 + (1.f - z2) * carry; out[ob + o2] = s2 * carry;
        carry = z3 * q3 + (1.f - z3) * carry; out[ob + o3] = s3 * carry;
    }
    const size_t coff = (size_t)64 << 16;
    zb += coff; hb += coff; sb += coff;
    carry = h21[c];
    for (int y = 252; y >= 0; y -= 4) {
        float z0, z1, z2, z3, q0, q1, q2, q3, s0, s1, s2, s3;
        size_t o0 = (size_t)y << 8, o1 = o0 + 256, o2 = o0 + 512, o3 = o0 + 768;
        z0 = g_zhs[zb + o0]; z1 = g_zhs[zb + o1]; z2 = g_zhs[zb + o2]; z3 = g_zhs[zb + o3];
        q0 = g_zhs[hb + o0]; q1 = g_zhs[hb + o1]; q2 = g_zhs[hb + o2]; q3 = g_zhs[hb + o3];
        s0 = g_zhs[sb + o0]; s1 = g_zhs[sb + o1]; s2 = g_zhs[sb + o2]; s3 = g_zhs[sb + o3];
        carry = z3 * q3 + (1.f - z3) * carry; out[ob + o3] += s3 * carry;
        carry = z2 * q2 + (1.f - z2) * carry; out[ob + o2] += s2 * carry;
        carry = z1 * q1 + (1.f - z1) * carry; out[ob + o1] += s1 * carry;
        carry = z0 * q0 + (1.f - z0) * carry; out[ob + o0] += s0 * carry;
    }
}

// ---------------------------------------------------------------------------
// Horizontal scans: warp per row, 8 elements/lane serial + one warp scan.
// Block = (b, c, ytile of 32): 8 warps x 4 rows each.
// ---------------------------------------------------------------------------
__global__ __launch_bounds__(256)
void scan_h_kernel(const float* __restrict__ h30,
                   const float* __restrict__ h31,
                   float* __restrict__ out)
{
    const int blk = blockIdx.x;          // 4 * 64 * 8 = 2048
    const int yt = blk & 7;
    const int c  = (blk >> 3) & 63;
    const int b  = blk >> 9;
    const int warp = threadIdx.x >> 5;
    const int lane = threadIdx.x & 31;

    const float hi30 = h30[c];
    const float hi31 = h31[c];

    const size_t zb2 = (((size_t)0 * B_ + b) * C4 + 128 + c) << 16;
    const size_t hb2 = (((size_t)1 * B_ + b) * C4 + 128 + c) << 16;
    const size_t sb2 = (((size_t)2 * B_ + b) * C4 + 128 + c) << 16;
    const size_t zb3 = (((size_t)0 * B_ + b) * C4 + 192 + c) << 16;
    const size_t hb3 = (((size_t)1 * B_ + b) * C4 + 192 + c) << 16;
    const size_t sb3 = (((size_t)2 * B_ + b) * C4 + 192 + c) << 16;
    const size_t ob  = ((size_t)b * 64 + c) << 16;

    for (int rr = 0; rr < 4; ++rr) {
        const int y = yt * 32 + warp * 4 + rr;
        const size_t ro = ((size_t)y << 8) + lane * 8;

        float res[8];

        // ---- group 2: forward scan ----
        {
            float4 zlo = *(const float4*)&g_zhs[zb2 + ro];
            float4 zhi = *(const float4*)&g_zhs[zb2 + ro + 4];
            float4 qlo = *(const float4*)&g_zhs[hb2 + ro];
            float4 qhi = *(const float4*)&g_zhs[hb2 + ro + 4];
            float zz[8] = {zlo.x, zlo.y, zlo.z, zlo.w, zhi.x, zhi.y, zhi.z, zhi.w};
            float qq[8] = {qlo.x, qlo.y, qlo.z, qlo.w, qhi.x, qhi.y, qhi.z, qhi.w};
            float A[8], Bv[8];
            float ra = 1.f, rb = 0.f;
#pragma unroll
            for (int i = 0; i < 8; ++i) {
                float ai = 1.f - zz[i];
                float bi = zz[i] * qq[i];
                rb = fmaf(ai, rb, bi);
                ra = ra * ai;
                A[i] = ra; Bv[i] = rb;
            }
            // inclusive warp scan (composition), then exclusive via shfl_up 1
            float ga = ra, gb = rb;
#pragma unroll
            for (int off = 1; off < 32; off <<= 1) {
                float pa = __shfl_up_sync(0xFFFFFFFFu, ga, off);
                float pb = __shfl_up_sync(0xFFFFFFFFu, gb, off);
                if (lane >= off) { gb = fmaf(ga, pb, gb); ga = ga * pa; }
            }
            float PA = __shfl_up_sync(0xFFFFFFFFu, ga, 1);
            float PB = __shfl_up_sync(0xFFFFFFFFu, gb, 1);
            if (lane == 0) { PA = 1.f; PB = 0.f; }
            float base = fmaf(PA, hi30, PB);      // state before this lane
            float4 slo = *(const float4*)&g_zhs[sb2 + ro];
            float4 shi = *(const float4*)&g_zhs[sb2 + ro + 4];
            float ss[8] = {slo.x, slo.y, slo.z, slo.w, shi.x, shi.y, shi.z, shi.w};
#pragma unroll
            for (int i = 0; i < 8; ++i)
                res[i] = ss[i] * fmaf(A[i], base, Bv[i]);
        }

        // ---- group 3: reverse scan (sequence = descending x) ----
        {
            float4 zlo = *(const float4*)&g_zhs[zb3 + ro];
            float4 zhi = *(const float4*)&g_zhs[zb3 + ro + 4];
            float4 qlo = *(const float4*)&g_zhs[hb3 + ro];
            float4 qhi = *(const float4*)&g_zhs[hb3 + ro + 4];
            float zz[8] = {zlo.x, zlo.y, zlo.z, zlo.w, zhi.x, zhi.y, zhi.z, zhi.w};
            float qq[8] = {qlo.x, qlo.y, qlo.z, qlo.w, qhi.x, qhi.y, qhi.z, qhi.w};
            float A[8], Bv[8];
            float ra = 1.f, rb = 0.f;
#pragma unroll
            for (int i = 7; i >= 0; --i) {
                float ai = 1.f - zz[i];
                float bi = zz[i] * qq[i];
                rb = fmaf(ai, rb, bi);
                ra = ra * ai;
                A[i] = ra; Bv[i] = rb;
            }
            float ga = ra, gb = rb;
#pragma unroll
            for (int off = 1; off < 32; off <<= 1) {
                float pa = __shfl_down_sync(0xFFFFFFFFu, ga, off);
                float pb = __shfl_down_sync(0xFFFFFFFFu, gb, off);
                if (lane + off < 32) { gb = fmaf(ga, pb, gb); ga = ga * pa; }
            }
            float PA = __shfl_down_sync(0xFFFFFFFFu, ga, 1);
            float PB = __shfl_down_sync(0xFFFFFFFFu, gb, 1);
            if (lane == 31) { PA = 1.f; PB = 0.f; }
            float base = fmaf(PA, hi31, PB);
            float4 slo = *(const float4*)&g_zhs[sb3 + ro];
            float4 shi = *(const float4*)&g_zhs[sb3 + ro + 4];
            float ss[8] = {slo.x, slo.y, slo.z, slo.w, shi.x, shi.y, shi.z, shi.w};
#pragma unroll
            for (int i = 0; i < 8; ++i)
                res[i] += ss[i] * fmaf(A[i], base, Bv[i]);
        }

        // ---- accumulate into out ----
        float4 olo = *(const float4*)&out[ob + ro];
        float4 ohi = *(const float4*)&out[ob + ro + 4];
        olo.x += res[0]; olo.y += res[1]; olo.z += res[2]; olo.w += res[3];
        ohi.x += res[4]; ohi.y += res[5]; ohi.z += res[6]; ohi.w += res[7];
        *(float4*)&out[ob + ro]     = olo;
        *(float4*)&out[ob + ro + 4] = ohi;
    }
}

// ---------------------------------------------------------------------------
extern "C" void kernel_launch(void* const* d_in, const int* in_sizes, int n_in,
                              void* d_out, int out_size)
{
    const float* xs = (const float*)d_in[0];

    ConvParams P;
    for (int s = 0; s < 3; ++s) {
        int base = 1 + s * 5;
        P.w[s] = (const float*)d_in[base + 0];
        P.g[s] = (const float*)d_in[base + 1];
        P.b[s] = (const float*)d_in[base + 2];
        P.m[s] = (const float*)d_in[base + 3];
        P.v[s] = (const float*)d_in[base + 4];
    }
    const float* h20 = (const float*)d_in[16];
    const float* h21 = (const float*)d_in[17];
    const float* h30 = (const float*)d_in[18];
    const float* h31 = (const float*)d_in[19];

    float* out = (float*)d_out;

    cudaFuncSetAttribute(conv_mma_kernel,
                         cudaFuncAttributeMaxDynamicSharedMemorySize, SMEM_BYTES);

    dim3 xgrid(2, 256, 4);
    xpose_kernel<<<xgrid, 256>>>(xs);

    prep_kernel<<<1728, 256>>>(P);

    dim3 cgrid(512, 6, 4);
    conv_mma_kernel<<<cgrid, 256, SMEM_BYTES>>>();

    scan_v_kernel<<<256, 256>>>(h20, h21, out);
    scan_h_kernel<<<2048, 256>>>(h30, h31, out);
}

// round 8
// speedup vs baseline: 7.3654x; 1.1624x over previous
#include <cuda_runtime.h>
#include <cuda_fp16.h>
#include <math.h>
#include <stdint.h>

// ---------------------------------------------------------------------------
// MiniGRUConv2d4 on GB300 (compute_103 PTX target -> legacy mma.sync path):
//   pass 1: transpose xs -> xh[b][y][x][ci] fp16
//   pass 2: 3x(conv3x3+BN[+sigmoid]) implicit GEMM, fp16 mma.sync.m16n8k16,
//           ldmatrix fragment loads (A non-trans, B non-trans on [n][k]),
//           halo tile cp.async'd once per CTA, weights via cp.async ring.
//   pass 3: vertical scans as two-phase segmented affine scan (8 segs of 32)
//   pass 4: horizontal scans (warp-per-row, 8 elem/lane serial) + combine
// ---------------------------------------------------------------------------

#define B_  4
#define CIN 64
#define C4  256

static __device__ float g_zhs[(size_t)3 * B_ * C4 * 256 * 256];     // z/h/s planes
static __device__ __align__(16) __half gXh[(size_t)B_ * 256 * 256 * 64];
static __device__ __align__(16) __half gWtH[768 * 576];
static __device__ float gBias[768];
static __device__ float2 gSeg[2 * 4 * 64 * 8 * 256];                 // seg (A,B)

struct ConvParams {
    const float* w[3];
    const float* g[3];
    const float* b[3];
    const float* m[3];
    const float* v[3];
};

// ---------------- fast sigmoid (no MUFU) ------------------------------------
__device__ __forceinline__ float fast_sigmoid(float x)
{
    float u = -1.44269504f * x;
    u = fminf(fmaxf(u, -60.f), 60.f);
    float fi = rintf(u);
    float f  = u - fi;
    float p = 1.54035304e-4f;
    p = fmaf(p, f, 1.33335581e-3f);
    p = fmaf(p, f, 9.61812910e-3f);
    p = fmaf(p, f, 5.55041087e-2f);
    p = fmaf(p, f, 2.40226507e-1f);
    p = fmaf(p, f, 6.93147181e-1f);
    p = fmaf(p, f, 1.0f);
    int ei = (int)fi;
    float e = __int_as_float(__float_as_int(p) + (ei << 23));
    float d = 1.0f + e;
    float r = __int_as_float(0x7EF311C3 - __float_as_int(d));
    r = r * (2.0f - d * r);
    r = r * (2.0f - d * r);
    r = r * (2.0f - d * r);
    return r;
}

// ---------------- small helpers ---------------------------------------------
__device__ __forceinline__ uint32_t smem_u32(const void* p)
{
    uint32_t a;
    asm("{ .reg .u64 t; cvta.to.shared.u64 t, %1; cvt.u32.u64 %0, t; }"
        : "=r"(a) : "l"(p));
    return a;
}
__device__ __forceinline__ void cp16(uint32_t dst, const void* src)
{
    size_t g = __cvta_generic_to_global(src);
    asm volatile("cp.async.cg.shared.global [%0], [%1], 16;"
                 :: "r"(dst), "l"(g) : "memory");
}
__device__ __forceinline__ void sts_zero16(uint32_t a)
{
    asm volatile("st.shared.v4.u32 [%0], {%1,%1,%1,%1};" :: "r"(a), "r"(0u) : "memory");
}
__device__ __forceinline__ void ldsm_x4(uint32_t& r0, uint32_t& r1,
                                        uint32_t& r2, uint32_t& r3, uint32_t a)
{
    asm volatile("ldmatrix.sync.aligned.m8n8.x4.shared.b16 {%0,%1,%2,%3}, [%4];"
                 : "=r"(r0), "=r"(r1), "=r"(r2), "=r"(r3) : "r"(a));
}

// ---------------------------------------------------------------------------
// Prep: fold BN into fp16 weights, k = r*64+ci ordering; fp32 bias.
// ---------------------------------------------------------------------------
__global__ void prep_kernel(ConvParams P)
{
    int idx = blockIdx.x * 256 + threadIdx.x;
    if (idx < 768) {
        int set = idx >> 8, co = idx & 255;
        float inv = P.g[set][co] * rsqrtf(P.v[set][co] + 1e-5f);
        gBias[idx] = P.b[set][co] - P.m[set][co] * inv;
    }
    if (idx < 768 * 576) {
        int co_g = idx / 576;
        int k    = idx - co_g * 576;
        int r    = k >> 6;
        int ci   = k & 63;
        int set  = co_g >> 8;
        int co   = co_g & 255;
        float inv = P.g[set][co] * rsqrtf(P.v[set][co] + 1e-5f);
        gWtH[idx] = __float2half_rn(P.w[set][(co * 64 + ci) * 9 + r] * inv);
    }
}

// ---------------------------------------------------------------------------
// Transpose xs [b][ci][y][x] fp32 -> gXh [b][y][x][ci] fp16.
// ---------------------------------------------------------------------------
__global__ __launch_bounds__(256)
void xpose_kernel(const float* __restrict__ xs)
{
    __shared__ float S[64][129];
    const int xt = blockIdx.x;
    const int y  = blockIdx.y;
    const int b  = blockIdx.z;
    const int tid = threadIdx.x;

    const float* src = xs + (((size_t)b * CIN) << 16) + (y << 8) + xt * 128;
#pragma unroll
    for (int p = 0; p < 8; ++p) {
        int idx = tid + (p << 8);
        int ci  = idx >> 5;
        int x4  = idx & 31;
        float4 v = *(const float4*)(src + (((size_t)ci) << 16) + (x4 << 2));
        S[ci][x4 * 4 + 0] = v.x;
        S[ci][x4 * 4 + 1] = v.y;
        S[ci][x4 * 4 + 2] = v.z;
        S[ci][x4 * 4 + 3] = v.w;
    }
    __syncthreads();

    __half* dst = gXh + ((((size_t)b * 256 + y) * 256) + xt * 128) * 64;
#pragma unroll
    for (int p = 0; p < 4; ++p) {
        int chunk = tid + (p << 8);
        int g = chunk & 7;
        int x = chunk >> 3;
        int c0 = g * 8;
        __half2 h0 = __floats2half2_rn(S[c0 + 0][x], S[c0 + 1][x]);
        __half2 h1 = __floats2half2_rn(S[c0 + 2][x], S[c0 + 3][x]);
        __half2 h2 = __floats2half2_rn(S[c0 + 4][x], S[c0 + 5][x]);
        __half2 h3 = __floats2half2_rn(S[c0 + 6][x], S[c0 + 7][x]);
        uint4 val;
        val.x = *(uint32_t*)&h0; val.y = *(uint32_t*)&h1;
        val.z = *(uint32_t*)&h2; val.w = *(uint32_t*)&h3;
        *(uint4*)(dst + (size_t)x * 64 + g * 8) = val;
    }
}

// ---------------------------------------------------------------------------
// Conv: CTA = 128 px x 128 couts, 8 warps (4m x 2n), warp 32co x 64px.
// ldmatrix (non-trans) fragment loads from swizzled smem. 2 CTAs/SM.
// ---------------------------------------------------------------------------
#define BT_STRIDE 132
#define BT_BYTES  (3 * BT_STRIDE * 128)          // 50688
#define A_BUF     8192
#define SMEM_BYTES (BT_BYTES + 4 * A_BUF)        // 83456

__global__ __launch_bounds__(256, 2)
void conv_mma_kernel()
{
    extern __shared__ char smem[];
    const uint32_t sB = smem_u32(smem);
    const uint32_t sA = sB + BT_BYTES;

    const int tid = threadIdx.x;
    const int l   = tid & 31;
    const int w   = tid >> 5;
    const int wm  = w >> 1;            // 0..3 (32 co each)
    const int wn  = w & 1;             // 0..1 (64 px each)

    const int bx = blockIdx.x;         // 0..511
    const int y0 = bx >> 1;
    const int x0 = (bx & 1) << 7;
    const int m0 = blockIdx.y << 7;    // 0..640
    const int b  = blockIdx.z;

    // ---- fill B halo tile (cp.async / zero-fill), part of group 0 ----
    for (int t = tid; t < 3120; t += 256) {
        int row  = t / 1040;
        int rem  = t - row * 1040;
        int slot = rem >> 3;
        int g    = rem & 7;
        int y    = y0 - 1 + row;
        int x    = x0 + slot - 1;
        uint32_t dst = sB + (uint32_t)(row * BT_STRIDE + slot) * 128
                     + (uint32_t)((g ^ (slot & 7)) << 4);
        if ((unsigned)y < 256u && (unsigned)x < 256u)
            cp16(dst, gXh + ((((size_t)b * 256 + y) * 256 + x) * 64 + g * 8));
        else
            sts_zero16(dst);
    }

    // ---- A ring producer: 128co x 32k fp16 per chunk ----
    auto issueA = [&](int kt2) {
        if (kt2 < 18) {
            uint32_t base = sA + (uint32_t)((kt2 & 3) * A_BUF);
            const __half* src = gWtH + (size_t)m0 * 576 + kt2 * 32;
#pragma unroll
            for (int p = 0; p < 2; ++p) {
                int chunk = tid + (p << 8);
                int co  = chunk >> 2;
                int kpg = chunk & 3;
                uint32_t wrd = (uint32_t)(co << 4)
                             + (uint32_t)((kpg ^ ((co >> 1) & 3)) << 2);
                cp16(base + (wrd << 2), src + (size_t)co * 576 + (kpg << 3));
            }
        }
        asm volatile("cp.async.commit_group;" ::: "memory");
    };

    issueA(0);
    issueA(1);
    issueA(2);

    // ---- per-lane ldmatrix address constants ----
    // A: rows cA = wm*32 + (l&15) and +16; k 16B-group = ks*2 + (l>>4)
    const int hiA   = l >> 4;
    const int cA0   = (wm << 5) + (l & 15);
    const int cA1   = cA0 + 16;
    const int xa0   = (cA0 >> 1) & 3;
    const int xa1   = (cA1 >> 1) & 3;
    const uint32_t aoff0 = (uint32_t)(cA0 << 6);
    const uint32_t aoff1 = (uint32_t)(cA1 << 6);
    // B: lanes 0-7: n0..7/grp ga; 8-15: n0..7/ga+1; 16-23: n8..15/ga; 24-31: n8..15/ga+1
    const int gsel  = (l >> 3) & 1;
    const int sbl   = (wn << 6) + (l & 7) + ((l >> 4) << 3);

    float acc[2][8][4];
#pragma unroll
    for (int mt = 0; mt < 2; ++mt)
#pragma unroll
        for (int nt = 0; nt < 8; ++nt)
#pragma unroll
            for (int c = 0; c < 4; ++c) acc[mt][nt][c] = 0.f;

    for (int kt = 0; kt < 18; ++kt) {
        asm volatile("cp.async.wait_group 2;" ::: "memory");
        __syncthreads();

        const uint32_t abuf = sA + (uint32_t)((kt & 3) * A_BUF);
        const int r   = kt >> 1;
        const int row = r / 3;
        const int dxp = r - row * 3;
        const uint32_t rowbase = sB + (uint32_t)(row * BT_STRIDE) * 128;

#pragma unroll
        for (int ks = 0; ks < 2; ++ks) {
            const int kg = (ks << 1) + hiA;           // A k-group for this lane
            uint32_t a0[4], a1[4];
            ldsm_x4(a0[0], a0[1], a0[2], a0[3],
                    abuf + aoff0 + (uint32_t)((kg ^ xa0) << 4));
            ldsm_x4(a1[0], a1[1], a1[2], a1[3],
                    abuf + aoff1 + (uint32_t)((kg ^ xa1) << 4));

            const int ga = ((kt & 1) << 2) + (ks << 1) + gsel;
#pragma unroll
            for (int ntp = 0; ntp < 4; ++ntp) {
                int slot = sbl + (ntp << 4) + dxp;
                uint32_t addr = rowbase + (uint32_t)(slot << 7)
                              + (uint32_t)((ga ^ (slot & 7)) << 4);
                uint32_t b0, b1, b2, b3;
                ldsm_x4(b0, b1, b2, b3, addr);    // non-trans: [n][k] storage

                const int nt0 = ntp << 1;
#pragma unroll
                for (int half = 0; half < 2; ++half) {
                    uint32_t bb0 = half ? b2 : b0;
                    uint32_t bb1 = half ? b3 : b1;
                    int nt = nt0 + half;
                    asm volatile(
                        "mma.sync.aligned.m16n8k16.row.col.f32.f16.f16.f32 "
                        "{%0,%1,%2,%3}, {%4,%5,%6,%7}, {%8,%9}, {%0,%1,%2,%3};"
                        : "+f"(acc[0][nt][0]), "+f"(acc[0][nt][1]),
                          "+f"(acc[0][nt][2]), "+f"(acc[0][nt][3])
                        : "r"(a0[0]), "r"(a0[1]), "r"(a0[2]), "r"(a0[3]),
                          "r"(bb0), "r"(bb1));
                    asm volatile(
                        "mma.sync.aligned.m16n8k16.row.col.f32.f16.f16.f32 "
                        "{%0,%1,%2,%3}, {%4,%5,%6,%7}, {%8,%9}, {%0,%1,%2,%3};"
                        : "+f"(acc[1][nt][0]), "+f"(acc[1][nt][1]),
                          "+f"(acc[1][nt][2]), "+f"(acc[1][nt][3])
                        : "r"(a1[0]), "r"(a1[1]), "r"(a1[2]), "r"(a1[3]),
                          "r"(bb0), "r"(bb1));
                }
            }
        }
        issueA(kt + 3);
    }

    // ---- epilogue: bias (+sigmoid), float2 stores ----
    const int set = m0 >> 8;
    const int chb = m0 & 255;
#pragma unroll
    for (int mt = 0; mt < 2; ++mt) {
#pragma unroll
        for (int rr = 0; rr < 2; ++rr) {
            int cloc = (wm << 5) + (mt << 4) + (l >> 2) + (rr << 3);
            float bias = gBias[m0 + cloc];
            int ch = chb + cloc;
            size_t base = ((((size_t)set * B_ + b) * C4 + ch) << 16)
                        + ((size_t)y0 << 8) + x0;
#pragma unroll
            for (int nt = 0; nt < 8; ++nt) {
                int n = (wn << 6) + (nt << 3) + ((l & 3) << 1);
                float v0 = acc[mt][nt][rr * 2 + 0] + bias;
                float v1 = acc[mt][nt][rr * 2 + 1] + bias;
                if (set != 1) { v0 = fast_sigmoid(v0); v1 = fast_sigmoid(v1); }
                *(float2*)&g_zhs[base + n] = make_float2(v0, v1);
            }
        }
    }
}

// ---------------------------------------------------------------------------
// Vertical scan phase A: per-segment affine composition (A,B) over 32 rows.
// grid: 4096 blocks x 256 thr; block = seg(8) | c(64) | b(4) | g(2).
// ---------------------------------------------------------------------------
__global__ __launch_bounds__(256)
void segscan_v_kernel()
{
    const int x   = threadIdx.x;
    const int blk = blockIdx.x;
    const int seg = blk & 7;
    const int c   = (blk >> 3) & 63;
    const int b   = (blk >> 9) & 3;
    const int g   = blk >> 11;

    const size_t zb = ((((size_t)0 * B_ + b) * C4 + g * 64 + c) << 16) + x;
    const size_t hb = ((((size_t)1 * B_ + b) * C4 + g * 64 + c) << 16) + x;

    float A = 1.f, Bv = 0.f;
    const int ybase = seg << 5;
    if (g == 0) {
#pragma unroll 8
        for (int i = 0; i < 32; ++i) {
            size_t off = (size_t)(ybase + i) << 8;
            float z  = g_zhs[zb + off];
            float hv = g_zhs[hb + off];
            float ai = 1.f - z;
            Bv = fmaf(ai, Bv, z * hv);
            A  = A * ai;
        }
    } else {
#pragma unroll 8
        for (int i = 31; i >= 0; --i) {
            size_t off = (size_t)(ybase + i) << 8;
            float z  = g_zhs[zb + off];
            float hv = g_zhs[hb + off];
            float ai = 1.f - z;
            Bv = fmaf(ai, Bv, z * hv);
            A  = A * ai;
        }
    }
    gSeg[(size_t)blk * 256 + x] = make_float2(A, Bv);
}

// ---------------------------------------------------------------------------
// Vertical scan phase B: fold segment prefixes, rescan 32 rows for both
// groups, write out = s0*h0 + s1*h1 (overwrites poisoned out).
// grid: 2048 blocks x 256; block = seg(8) | c(64) | b(4).
// ---------------------------------------------------------------------------
__global__ __launch_bounds__(256)
void applyscan_v_kernel(const float* __restrict__ h20,
                        const float* __restrict__ h21,
                        float* __restrict__ out)
{
    const int x   = threadIdx.x;
    const int blk = blockIdx.x;
    const int seg = blk & 7;
    const int c   = (blk >> 3) & 63;
    const int b   = blk >> 9;

    float st0 = h20[c];
    {
        const size_t base = ((size_t)((0 * 4 + b) * 64 + c) * 8) * 256 + x;
        for (int k = 0; k < seg; ++k) {
            float2 f = gSeg[base + (size_t)k * 256];
            st0 = fmaf(f.x, st0, f.y);
        }
    }
    float st1 = h21[c];
    {
        const size_t base = ((size_t)((1 * 4 + b) * 64 + c) * 8) * 256 + x;
        for (int k = 7; k > seg; --k) {
            float2 f = gSeg[base + (size_t)k * 256];
            st1 = fmaf(f.x, st1, f.y);
        }
    }

    const int ybase = seg << 5;
    const size_t zb0 = ((((size_t)0 * B_ + b) * C4 + c) << 16) + x;
    const size_t hb0 = ((((size_t)1 * B_ + b) * C4 + c) << 16) + x;
    const size_t sb0 = ((((size_t)2 * B_ + b) * C4 + c) << 16) + x;
    const size_t coff = (size_t)64 << 16;
    const size_t ob  = (((size_t)b * 64 + c) << 16) + x;

    float r[32];
#pragma unroll
    for (int i = 0; i < 32; ++i) {
        size_t off = (size_t)(ybase + i) << 8;
        float z  = g_zhs[zb0 + off];
        float hv = g_zhs[hb0 + off];
        float s  = g_zhs[sb0 + off];
        st0 = z * hv + (1.f - z) * st0;
        r[i] = s * st0;
    }
#pragma unroll
    for (int i = 31; i >= 0; --i) {
        size_t off = (size_t)(ybase + i) << 8;
        float z  = g_zhs[zb0 + coff + off];
        float hv = g_zhs[hb0 + coff + off];
        float s  = g_zhs[sb0 + coff + off];
        st1 = z * hv + (1.f - z) * st1;
        r[i] += s * st1;
    }
#pragma unroll
    for (int i = 0; i < 32; ++i)
        out[ob + ((size_t)(ybase + i) << 8)] = r[i];
}

// ---------------------------------------------------------------------------
// Horizontal scans: warp per row, 8 elements/lane serial + one warp scan.
// ---------------------------------------------------------------------------
__global__ __launch_bounds__(256)
void scan_h_kernel(const float* __restrict__ h30,
                   const float* __restrict__ h31,
                   float* __restrict__ out)
{
    const int blk = blockIdx.x;          // 4 * 64 * 8 = 2048
    const int yt = blk & 7;
    const int c  = (blk >> 3) & 63;
    const int b  = blk >> 9;
    const int warp = threadIdx.x >> 5;
    const int lane = threadIdx.x & 31;

    const float hi30 = h30[c];
    const float hi31 = h31[c];

    const size_t zb2 = (((size_t)0 * B_ + b) * C4 + 128 + c) << 16;
    const size_t hb2 = (((size_t)1 * B_ + b) * C4 + 128 + c) << 16;
    const size_t sb2 = (((size_t)2 * B_ + b) * C4 + 128 + c) << 16;
    const size_t zb3 = (((size_t)0 * B_ + b) * C4 + 192 + c) << 16;
    const size_t hb3 = (((size_t)1 * B_ + b) * C4 + 192 + c) << 16;
    const size_t sb3 = (((size_t)2 * B_ + b) * C4 + 192 + c) << 16;
    const size_t ob  = ((size_t)b * 64 + c) << 16;

    for (int rr = 0; rr < 4; ++rr) {
        const int y = yt * 32 + warp * 4 + rr;
        const size_t ro = ((size_t)y << 8) + lane * 8;

        float res[8];

        // ---- group 2: forward scan ----
        {
            float4 zlo = *(const float4*)&g_zhs[zb2 + ro];
            float4 zhi = *(const float4*)&g_zhs[zb2 + ro + 4];
            float4 qlo = *(const float4*)&g_zhs[hb2 + ro];
            float4 qhi = *(const float4*)&g_zhs[hb2 + ro + 4];
            float zz[8] = {zlo.x, zlo.y, zlo.z, zlo.w, zhi.x, zhi.y, zhi.z, zhi.w};
            float qq[8] = {qlo.x, qlo.y, qlo.z, qlo.w, qhi.x, qhi.y, qhi.z, qhi.w};
            float A[8], Bv[8];
            float ra = 1.f, rb = 0.f;
#pragma unroll
            for (int i = 0; i < 8; ++i) {
                float ai = 1.f - zz[i];
                float bi = zz[i] * qq[i];
                rb = fmaf(ai, rb, bi);
                ra = ra * ai;
                A[i] = ra; Bv[i] = rb;
            }
            float ga = ra, gb = rb;
#pragma unroll
            for (int off = 1; off < 32; off <<= 1) {
                float pa = __shfl_up_sync(0xFFFFFFFFu, ga, off);
                float pb = __shfl_up_sync(0xFFFFFFFFu, gb, off);
                if (lane >= off) { gb = fmaf(ga, pb, gb); ga = ga * pa; }
            }
            float PA = __shfl_up_sync(0xFFFFFFFFu, ga, 1);
            float PB = __shfl_up_sync(0xFFFFFFFFu, gb, 1);
            if (lane == 0) { PA = 1.f; PB = 0.f; }
            float base = fmaf(PA, hi30, PB);
            float4 slo = *(const float4*)&g_zhs[sb2 + ro];
            float4 shi = *(const float4*)&g_zhs[sb2 + ro + 4];
            float ss[8] = {slo.x, slo.y, slo.z, slo.w, shi.x, shi.y, shi.z, shi.w};
#pragma unroll
            for (int i = 0; i < 8; ++i)
                res[i] = ss[i] * fmaf(A[i], base, Bv[i]);
        }

        // ---- group 3: reverse scan ----
        {
            float4 zlo = *(const float4*)&g_zhs[zb3 + ro];
            float4 zhi = *(const float4*)&g_zhs[zb3 + ro + 4];
            float4 qlo = *(const float4*)&g_zhs[hb3 + ro];
            float4 qhi = *(const float4*)&g_zhs[hb3 + ro + 4];
            float zz[8] = {zlo.x, zlo.y, zlo.z, zlo.w, zhi.x, zhi.y, zhi.z, zhi.w};
            float qq[8] = {qlo.x, qlo.y, qlo.z, qlo.w, qhi.x, qhi.y, qhi.z, qhi.w};
            float A[8], Bv[8];
            float ra = 1.f, rb = 0.f;
#pragma unroll
            for (int i = 7; i >= 0; --i) {
                float ai = 1.f - zz[i];
                float bi = zz[i] * qq[i];
                rb = fmaf(ai, rb, bi);
                ra = ra * ai;
                A[i] = ra; Bv[i] = rb;
            }
            float ga = ra, gb = rb;
#pragma unroll
            for (int off = 1; off < 32; off <<= 1) {
                float pa = __shfl_down_sync(0xFFFFFFFFu, ga, off);
                float pb = __shfl_down_sync(0xFFFFFFFFu, gb, off);
                if (lane + off < 32) { gb = fmaf(ga, pb, gb); ga = ga * pa; }
            }
            float PA = __shfl_down_sync(0xFFFFFFFFu, ga, 1);
            float PB = __shfl_down_sync(0xFFFFFFFFu, gb, 1);
            if (lane == 31) { PA = 1.f; PB = 0.f; }
            float base = fmaf(PA, hi31, PB);
            float4 slo = *(const float4*)&g_zhs[sb3 + ro];
            float4 shi = *(const float4*)&g_zhs[sb3 + ro + 4];
            float ss[8] = {slo.x, slo.y, slo.z, slo.w, shi.x, shi.y, shi.z, shi.w};
#pragma unroll
            for (int i = 0; i < 8; ++i)
                res[i] += ss[i] * fmaf(A[i], base, Bv[i]);
        }

        float4 olo = *(const float4*)&out[ob + ro];
        float4 ohi = *(const float4*)&out[ob + ro + 4];
        olo.x += res[0]; olo.y += res[1]; olo.z += res[2]; olo.w += res[3];
        ohi.x += res[4]; ohi.y += res[5]; ohi.z += res[6]; ohi.w += res[7];
        *(float4*)&out[ob + ro]     = olo;
        *(float4*)&out[ob + ro + 4] = ohi;
    }
}

// ---------------------------------------------------------------------------
extern "C" void kernel_launch(void* const* d_in, const int* in_sizes, int n_in,
                              void* d_out, int out_size)
{
    const float* xs = (const float*)d_in[0];

    ConvParams P;
    for (int s = 0; s < 3; ++s) {
        int base = 1 + s * 5;
        P.w[s] = (const float*)d_in[base + 0];
        P.g[s] = (const float*)d_in[base + 1];
        P.b[s] = (const float*)d_in[base + 2];
        P.m[s] = (const float*)d_in[base + 3];
        P.v[s] = (const float*)d_in[base + 4];
    }
    const float* h20 = (const float*)d_in[16];
    const float* h21 = (const float*)d_in[17];
    const float* h30 = (const float*)d_in[18];
    const float* h31 = (const float*)d_in[19];

    float* out = (float*)d_out;

    cudaFuncSetAttribute(conv_mma_kernel,
                         cudaFuncAttributeMaxDynamicSharedMemorySize, SMEM_BYTES);

    dim3 xgrid(2, 256, 4);
    xpose_kernel<<<xgrid, 256>>>(xs);

    prep_kernel<<<1728, 256>>>(P);

    dim3 cgrid(512, 6, 4);
    conv_mma_kernel<<<cgrid, 256, SMEM_BYTES>>>();

    segscan_v_kernel<<<4096, 256>>>();
    applyscan_v_kernel<<<2048, 256>>>(h20, h21, out);
    scan_h_kernel<<<2048, 256>>>(h30, h31, out);
}

// round 9
// speedup vs baseline: 8.1257x; 1.1032x over previous
#include <cuda_runtime.h>
#include <cuda_fp16.h>
#include <math.h>
#include <stdint.h>

// ---------------------------------------------------------------------------
// MiniGRUConv2d4 on GB300 (compute_103 PTX target -> legacy mma.sync path):
//   pass 1: transpose xs -> xh[b][y][x][ci] fp16
//   pass 2: 3x(conv3x3+BN[+sigmoid]) implicit GEMM, fp16 mma.sync.m16n8k16,
//           ldmatrix fragment loads, progressive halo staging, weights via
//           cp.async ring. z/s planes stored fp16, h plane fp32.
//   pass 3: vertical scans: segment compose + fused apply/horizontal tail.
// ---------------------------------------------------------------------------

#define B_  4
#define CIN 64
#define C4  256

static __device__ float  gH[(size_t)B_ * C4 * 256 * 256];            // h plane
static __device__ __half gZ[(size_t)B_ * C4 * 256 * 256];            // z plane
static __device__ __half gS[(size_t)B_ * C4 * 256 * 256];            // s plane
static __device__ __align__(16) __half gXh[(size_t)B_ * 256 * 256 * 64];
static __device__ __align__(16) __half gWtH[768 * 576];
static __device__ float gBias[768];
static __device__ float2 gSeg[2 * 4 * 64 * 8 * 256];                 // seg (A,B)

struct ConvParams {
    const float* w[3];
    const float* g[3];
    const float* b[3];
    const float* m[3];
    const float* v[3];
};

// ---------------- fast sigmoid (no MUFU) ------------------------------------
__device__ __forceinline__ float fast_sigmoid(float x)
{
    float u = -1.44269504f * x;
    u = fminf(fmaxf(u, -60.f), 60.f);
    float fi = rintf(u);
    float f  = u - fi;
    float p = 1.54035304e-4f;
    p = fmaf(p, f, 1.33335581e-3f);
    p = fmaf(p, f, 9.61812910e-3f);
    p = fmaf(p, f, 5.55041087e-2f);
    p = fmaf(p, f, 2.40226507e-1f);
    p = fmaf(p, f, 6.93147181e-1f);
    p = fmaf(p, f, 1.0f);
    int ei = (int)fi;
    float e = __int_as_float(__float_as_int(p) + (ei << 23));
    float d = 1.0f + e;
    float r = __int_as_float(0x7EF311C3 - __float_as_int(d));
    r = r * (2.0f - d * r);
    r = r * (2.0f - d * r);
    r = r * (2.0f - d * r);
    return r;
}

// ---------------- small helpers ---------------------------------------------
__device__ __forceinline__ uint32_t smem_u32(const void* p)
{
    uint32_t a;
    asm("{ .reg .u64 t; cvta.to.shared.u64 t, %1; cvt.u32.u64 %0, t; }"
        : "=r"(a) : "l"(p));
    return a;
}
__device__ __forceinline__ void cp16(uint32_t dst, const void* src)
{
    size_t g = __cvta_generic_to_global(src);
    asm volatile("cp.async.cg.shared.global [%0], [%1], 16;"
                 :: "r"(dst), "l"(g) : "memory");
}
__device__ __forceinline__ void sts_zero16(uint32_t a)
{
    asm volatile("st.shared.v4.u32 [%0], {%1,%1,%1,%1};" :: "r"(a), "r"(0u) : "memory");
}
__device__ __forceinline__ void ldsm_x4(uint32_t& r0, uint32_t& r1,
                                        uint32_t& r2, uint32_t& r3, uint32_t a)
{
    asm volatile("ldmatrix.sync.aligned.m8n8.x4.shared.b16 {%0,%1,%2,%3}, [%4];"
                 : "=r"(r0), "=r"(r1), "=r"(r2), "=r"(r3) : "r"(a));
}
// load 8 consecutive halves -> 8 floats
__device__ __forceinline__ void ld8h(const __half* p, float* d)
{
    uint4 u = *(const uint4*)p;
    const __half2* h = (const __half2*)&u;
    float2 f0 = __half22float2(h[0]);
    float2 f1 = __half22float2(h[1]);
    float2 f2 = __half22float2(h[2]);
    float2 f3 = __half22float2(h[3]);
    d[0] = f0.x; d[1] = f0.y; d[2] = f1.x; d[3] = f1.y;
    d[4] = f2.x; d[5] = f2.y; d[6] = f3.x; d[7] = f3.y;
}

// ---------------------------------------------------------------------------
// Prep: fold BN into fp16 weights, k = r*64+ci ordering; fp32 bias.
// ---------------------------------------------------------------------------
__global__ void prep_kernel(ConvParams P)
{
    int idx = blockIdx.x * 256 + threadIdx.x;
    if (idx < 768) {
        int set = idx >> 8, co = idx & 255;
        float inv = P.g[set][co] * rsqrtf(P.v[set][co] + 1e-5f);
        gBias[idx] = P.b[set][co] - P.m[set][co] * inv;
    }
    if (idx < 768 * 576) {
        int co_g = idx / 576;
        int k    = idx - co_g * 576;
        int r    = k >> 6;
        int ci   = k & 63;
        int set  = co_g >> 8;
        int co   = co_g & 255;
        float inv = P.g[set][co] * rsqrtf(P.v[set][co] + 1e-5f);
        gWtH[idx] = __float2half_rn(P.w[set][(co * 64 + ci) * 9 + r] * inv);
    }
}

// ---------------------------------------------------------------------------
// Transpose xs [b][ci][y][x] fp32 -> gXh [b][y][x][ci] fp16.
// ---------------------------------------------------------------------------
__global__ __launch_bounds__(256)
void xpose_kernel(const float* __restrict__ xs)
{
    __shared__ float S[64][129];
    const int xt = blockIdx.x;
    const int y  = blockIdx.y;
    const int b  = blockIdx.z;
    const int tid = threadIdx.x;

    const float* src = xs + (((size_t)b * CIN) << 16) + (y << 8) + xt * 128;
#pragma unroll
    for (int p = 0; p < 8; ++p) {
        int idx = tid + (p << 8);
        int ci  = idx >> 5;
        int x4  = idx & 31;
        float4 v = *(const float4*)(src + (((size_t)ci) << 16) + (x4 << 2));
        S[ci][x4 * 4 + 0] = v.x;
        S[ci][x4 * 4 + 1] = v.y;
        S[ci][x4 * 4 + 2] = v.z;
        S[ci][x4 * 4 + 3] = v.w;
    }
    __syncthreads();

    __half* dst = gXh + ((((size_t)b * 256 + y) * 256) + xt * 128) * 64;
#pragma unroll
    for (int p = 0; p < 4; ++p) {
        int chunk = tid + (p << 8);
        int g = chunk & 7;
        int x = chunk >> 3;
        int c0 = g * 8;
        __half2 h0 = __floats2half2_rn(S[c0 + 0][x], S[c0 + 1][x]);
        __half2 h1 = __floats2half2_rn(S[c0 + 2][x], S[c0 + 3][x]);
        __half2 h2 = __floats2half2_rn(S[c0 + 4][x], S[c0 + 5][x]);
        __half2 h3 = __floats2half2_rn(S[c0 + 6][x], S[c0 + 7][x]);
        uint4 val;
        val.x = *(uint32_t*)&h0; val.y = *(uint32_t*)&h1;
        val.z = *(uint32_t*)&h2; val.w = *(uint32_t*)&h3;
        *(uint4*)(dst + (size_t)x * 64 + g * 8) = val;
    }
}

// ---------------------------------------------------------------------------
// Conv: CTA = 128 px x 128 couts, 8 warps (4m x 2n), warp 32co x 64px.
// ldmatrix fragment loads; progressive halo staging; 2 CTAs/SM.
// ---------------------------------------------------------------------------
#define BT_STRIDE 132
#define BT_BYTES  (3 * BT_STRIDE * 128)          // 50688
#define A_BUF     8192
#define SMEM_BYTES (BT_BYTES + 4 * A_BUF)        // 83456

__global__ __launch_bounds__(256, 2)
void conv_mma_kernel()
{
    extern __shared__ char smem[];
    const uint32_t sB = smem_u32(smem);
    const uint32_t sA = sB + BT_BYTES;

    const int tid = threadIdx.x;
    const int l   = tid & 31;
    const int w   = tid >> 5;
    const int wm  = w >> 1;            // 0..3 (32 co each)
    const int wn  = w & 1;             // 0..1 (64 px each)

    const int bx = blockIdx.x;         // 0..511
    const int y0 = bx >> 1;
    const int x0 = (bx & 1) << 7;
    const int m0 = blockIdx.y << 7;    // 0..640
    const int b  = blockIdx.z;

    // ---- A ring producer: 128co x 32k fp16 per chunk ----
    auto issueA = [&](int kt2) {
        if (kt2 < 18) {
            uint32_t base = sA + (uint32_t)((kt2 & 3) * A_BUF);
            const __half* src = gWtH + (size_t)m0 * 576 + kt2 * 32;
#pragma unroll
            for (int p = 0; p < 2; ++p) {
                int chunk = tid + (p << 8);
                int co  = chunk >> 2;
                int kpg = chunk & 3;
                uint32_t wrd = (uint32_t)(co << 4)
                             + (uint32_t)((kpg ^ ((co >> 1) & 3)) << 2);
                cp16(base + (wrd << 2), src + (size_t)co * 576 + (kpg << 3));
            }
        }
        asm volatile("cp.async.commit_group;" ::: "memory");
    };

    // ---- progressive B halo fill: row r goes in cp.async group r ----
    for (int row = 0; row < 3; ++row) {
        const int y = y0 - 1 + row;
        const bool rok = (unsigned)y < 256u;
        for (int t = tid; t < 1040; t += 256) {
            int slot = t >> 3;
            int g    = t & 7;
            int x    = x0 + slot - 1;
            uint32_t dst = sB + (uint32_t)(row * BT_STRIDE + slot) * 128
                         + (uint32_t)((g ^ (slot & 7)) << 4);
            if (rok && (unsigned)x < 256u)
                cp16(dst, gXh + ((((size_t)b * 256 + y) * 256 + x) * 64 + g * 8));
            else
                sts_zero16(dst);
        }
        issueA(row);
    }

    // ---- per-lane ldmatrix address constants ----
    const int hiA   = l >> 4;
    const int cA0   = (wm << 5) + (l & 15);
    const int cA1   = cA0 + 16;
    const int xa0   = (cA0 >> 1) & 3;
    const int xa1   = (cA1 >> 1) & 3;
    const uint32_t aoff0 = (uint32_t)(cA0 << 6);
    const uint32_t aoff1 = (uint32_t)(cA1 << 6);
    const int gsel  = (l >> 3) & 1;
    const int sbl   = (wn << 6) + (l & 7) + ((l >> 4) << 3);

    float acc[2][8][4];
#pragma unroll
    for (int mt = 0; mt < 2; ++mt)
#pragma unroll
        for (int nt = 0; nt < 8; ++nt)
#pragma unroll
            for (int c = 0; c < 4; ++c) acc[mt][nt][c] = 0.f;

    for (int kt = 0; kt < 18; ++kt) {
        asm volatile("cp.async.wait_group 2;" ::: "memory");
        __syncthreads();

        const uint32_t abuf = sA + (uint32_t)((kt & 3) * A_BUF);
        const int r   = kt >> 1;
        const int row = r / 3;
        const int dxp = r - row * 3;
        const uint32_t rowbase = sB + (uint32_t)(row * BT_STRIDE) * 128;

#pragma unroll
        for (int ks = 0; ks < 2; ++ks) {
            const int kg = (ks << 1) + hiA;
            uint32_t a0[4], a1[4];
            ldsm_x4(a0[0], a0[1], a0[2], a0[3],
                    abuf + aoff0 + (uint32_t)((kg ^ xa0) << 4));
            ldsm_x4(a1[0], a1[1], a1[2], a1[3],
                    abuf + aoff1 + (uint32_t)((kg ^ xa1) << 4));

            const int ga = ((kt & 1) << 2) + (ks << 1) + gsel;
#pragma unroll
            for (int ntp = 0; ntp < 4; ++ntp) {
                int slot = sbl + (ntp << 4) + dxp;
                uint32_t addr = rowbase + (uint32_t)(slot << 7)
                              + (uint32_t)((ga ^ (slot & 7)) << 4);
                uint32_t b0, b1, b2, b3;
                ldsm_x4(b0, b1, b2, b3, addr);

                const int nt0 = ntp << 1;
#pragma unroll
                for (int half = 0; half < 2; ++half) {
                    uint32_t bb0 = half ? b2 : b0;
                    uint32_t bb1 = half ? b3 : b1;
                    int nt = nt0 + half;
                    asm volatile(
                        "mma.sync.aligned.m16n8k16.row.col.f32.f16.f16.f32 "
                        "{%0,%1,%2,%3}, {%4,%5,%6,%7}, {%8,%9}, {%0,%1,%2,%3};"
                        : "+f"(acc[0][nt][0]), "+f"(acc[0][nt][1]),
                          "+f"(acc[0][nt][2]), "+f"(acc[0][nt][3])
                        : "r"(a0[0]), "r"(a0[1]), "r"(a0[2]), "r"(a0[3]),
                          "r"(bb0), "r"(bb1));
                    asm volatile(
                        "mma.sync.aligned.m16n8k16.row.col.f32.f16.f16.f32 "
                        "{%0,%1,%2,%3}, {%4,%5,%6,%7}, {%8,%9}, {%0,%1,%2,%3};"
                        : "+f"(acc[1][nt][0]), "+f"(acc[1][nt][1]),
                          "+f"(acc[1][nt][2]), "+f"(acc[1][nt][3])
                        : "r"(a1[0]), "r"(a1[1]), "r"(a1[2]), "r"(a1[3]),
                          "r"(bb0), "r"(bb1));
                }
            }
        }
        issueA(kt + 3);
    }

    // ---- epilogue: bias; set1 -> gH fp32; set0/2 -> gZ/gS fp16 + sigmoid ----
    const int set = m0 >> 8;
    const int chb = m0 & 255;
#pragma unroll
    for (int mt = 0; mt < 2; ++mt) {
#pragma unroll
        for (int rr = 0; rr < 2; ++rr) {
            int cloc = (wm << 5) + (mt << 4) + (l >> 2) + (rr << 3);
            float bias = gBias[m0 + cloc];
            int ch = chb + cloc;
            size_t base = (((size_t)b * C4 + ch) << 16) + ((size_t)y0 << 8) + x0;
#pragma unroll
            for (int nt = 0; nt < 8; ++nt) {
                int n = (wn << 6) + (nt << 3) + ((l & 3) << 1);
                float v0 = acc[mt][nt][rr * 2 + 0] + bias;
                float v1 = acc[mt][nt][rr * 2 + 1] + bias;
                if (set == 1) {
                    *(float2*)&gH[base + n] = make_float2(v0, v1);
                } else {
                    __half2 h2 = __floats2half2_rn(fast_sigmoid(v0),
                                                   fast_sigmoid(v1));
                    if (set == 0) *(__half2*)&gZ[base + n] = h2;
                    else          *(__half2*)&gS[base + n] = h2;
                }
            }
        }
    }
}

// ---------------------------------------------------------------------------
// Vertical scan phase A: per-segment affine composition (A,B) over 32 rows.
// grid: 4096 blocks x 256 thr; block = seg(8) | c(64) | b(4) | g(2).
// ---------------------------------------------------------------------------
__global__ __launch_bounds__(256)
void segscan_v_kernel()
{
    const int x   = threadIdx.x;
    const int blk = blockIdx.x;
    const int seg = blk & 7;
    const int c   = (blk >> 3) & 63;
    const int b   = (blk >> 9) & 3;
    const int g   = blk >> 11;

    const size_t pb = (((size_t)b * C4 + g * 64 + c) << 16) + x;

    float A = 1.f, Bv = 0.f;
    const int ybase = seg << 5;
    if (g == 0) {
#pragma unroll 8
        for (int i = 0; i < 32; ++i) {
            size_t off = (size_t)(ybase + i) << 8;
            float z  = __half2float(gZ[pb + off]);
            float hv = gH[pb + off];
            float ai = 1.f - z;
            Bv = fmaf(ai, Bv, z * hv);
            A  = A * ai;
        }
    } else {
#pragma unroll 8
        for (int i = 31; i >= 0; --i) {
            size_t off = (size_t)(ybase + i) << 8;
            float z  = __half2float(gZ[pb + off]);
            float hv = gH[pb + off];
            float ai = 1.f - z;
            Bv = fmaf(ai, Bv, z * hv);
            A  = A * ai;
        }
    }
    gSeg[(size_t)blk * 256 + x] = make_float2(A, Bv);
}

// ---------------------------------------------------------------------------
// Fused tail: vertical apply (groups 0,1) into smem, then horizontal scans
// (groups 2,3) per row, single write of out. Block = seg(8) | c(64) | b(4).
// ---------------------------------------------------------------------------
__global__ __launch_bounds__(256)
void scan_tail_kernel(const float* __restrict__ h20,
                      const float* __restrict__ h21,
                      const float* __restrict__ h30,
                      const float* __restrict__ h31,
                      float* __restrict__ out)
{
    __shared__ float Sbuf[256][33];

    const int blk = blockIdx.x;
    const int seg = blk & 7;
    const int c   = (blk >> 3) & 63;
    const int b   = blk >> 9;
    const int tid = threadIdx.x;
    const int warp = tid >> 5;
    const int lane = tid & 31;

    // ================= part 1: vertical apply for column x = tid ===========
    {
        const int x = tid;
        float st0 = h20[c];
        {
            const size_t base = ((size_t)((0 * 4 + b) * 64 + c) * 8) * 256 + x;
            for (int k = 0; k < seg; ++k) {
                float2 f = gSeg[base + (size_t)k * 256];
                st0 = fmaf(f.x, st0, f.y);
            }
        }
        float st1 = h21[c];
        {
            const size_t base = ((size_t)((1 * 4 + b) * 64 + c) * 8) * 256 + x;
            for (int k = 7; k > seg; --k) {
                float2 f = gSeg[base + (size_t)k * 256];
                st1 = fmaf(f.x, st1, f.y);
            }
        }

        const int ybase = seg << 5;
        const size_t p0 = (((size_t)b * C4 + c) << 16) + x;         // group 0
        const size_t p1 = p0 + ((size_t)64 << 16);                  // group 1

#pragma unroll
        for (int i = 0; i < 32; ++i) {
            size_t off = (size_t)(ybase + i) << 8;
            float z  = __half2float(gZ[p0 + off]);
            float hv = gH[p0 + off];
            float s  = __half2float(gS[p0 + off]);
            st0 = z * hv + (1.f - z) * st0;
            Sbuf[x][i] = s * st0;
        }
#pragma unroll
        for (int i = 31; i >= 0; --i) {
            size_t off = (size_t)(ybase + i) << 8;
            float z  = __half2float(gZ[p1 + off]);
            float hv = gH[p1 + off];
            float s  = __half2float(gS[p1 + off]);
            st1 = z * hv + (1.f - z) * st1;
            Sbuf[x][i] += s * st1;
        }
    }
    __syncthreads();

    // ================= part 2: horizontal scans, rows of this seg ==========
    const float hi30 = h30[c];
    const float hi31 = h31[c];
    const size_t p2 = ((size_t)b * C4 + 128 + c) << 16;             // group 2
    const size_t p3 = ((size_t)b * C4 + 192 + c) << 16;             // group 3
    const size_t ob = ((size_t)b * 64 + c) << 16;

    for (int rr = 0; rr < 4; ++rr) {
        const int rloc = warp * 4 + rr;                 // 0..31
        const int y = (seg << 5) + rloc;
        const size_t ro = ((size_t)y << 8) + lane * 8;

        float res[8];

        // ---- group 2: forward scan ----
        {
            float zz[8], ss[8];
            ld8h(&gZ[p2 + ro], zz);
            float4 qlo = *(const float4*)&gH[p2 + ro];
            float4 qhi = *(const float4*)&gH[p2 + ro + 4];
            float qq[8] = {qlo.x, qlo.y, qlo.z, qlo.w, qhi.x, qhi.y, qhi.z, qhi.w};
            float A[8], Bv[8];
            float ra = 1.f, rb = 0.f;
#pragma unroll
            for (int i = 0; i < 8; ++i) {
                float ai = 1.f - zz[i];
                float bi = zz[i] * qq[i];
                rb = fmaf(ai, rb, bi);
                ra = ra * ai;
                A[i] = ra; Bv[i] = rb;
            }
            float ga = ra, gb = rb;
#pragma unroll
            for (int off = 1; off < 32; off <<= 1) {
                float pa = __shfl_up_sync(0xFFFFFFFFu, ga, off);
                float pb = __shfl_up_sync(0xFFFFFFFFu, gb, off);
                if (lane >= off) { gb = fmaf(ga, pb, gb); ga = ga * pa; }
            }
            float PA = __shfl_up_sync(0xFFFFFFFFu, ga, 1);
            float PB = __shfl_up_sync(0xFFFFFFFFu, gb, 1);
            if (lane == 0) { PA = 1.f; PB = 0.f; }
            float base = fmaf(PA, hi30, PB);
            ld8h(&gS[p2 + ro], ss);
#pragma unroll
            for (int i = 0; i < 8; ++i)
                res[i] = ss[i] * fmaf(A[i], base, Bv[i]);
        }

        // ---- group 3: reverse scan ----
        {
            float zz[8], ss[8];
            ld8h(&gZ[p3 + ro], zz);
            float4 qlo = *(const float4*)&gH[p3 + ro];
            float4 qhi = *(const float4*)&gH[p3 + ro + 4];
            float qq[8] = {qlo.x, qlo.y, qlo.z, qlo.w, qhi.x, qhi.y, qhi.z, qhi.w};
            float A[8], Bv[8];
            float ra = 1.f, rb = 0.f;
#pragma unroll
            for (int i = 7; i >= 0; --i) {
                float ai = 1.f - zz[i];
                float bi = zz[i] * qq[i];
                rb = fmaf(ai, rb, bi);
                ra = ra * ai;
                A[i] = ra; Bv[i] = rb;
            }
            float ga = ra, gb = rb;
#pragma unroll
            for (int off = 1; off < 32; off <<= 1) {
                float pa = __shfl_down_sync(0xFFFFFFFFu, ga, off);
                float pb = __shfl_down_sync(0xFFFFFFFFu, gb, off);
                if (lane + off < 32) { gb = fmaf(ga, pb, gb); ga = ga * pa; }
            }
            float PA = __shfl_down_sync(0xFFFFFFFFu, ga, 1);
            float PB = __shfl_down_sync(0xFFFFFFFFu, gb, 1);
            if (lane == 31) { PA = 1.f; PB = 0.f; }
            float base = fmaf(PA, hi31, PB);
            ld8h(&gS[p3 + ro], ss);
#pragma unroll
            for (int i = 0; i < 8; ++i)
                res[i] += ss[i] * fmaf(A[i], base, Bv[i]);
        }

        // ---- add vertical part from smem, single store ----
        float4 olo, ohi;
        olo.x = res[0] + Sbuf[lane * 8 + 0][rloc];
        olo.y = res[1] + Sbuf[lane * 8 + 1][rloc];
        olo.z = res[2] + Sbuf[lane * 8 + 2][rloc];
        olo.w = res[3] + Sbuf[lane * 8 + 3][rloc];
        ohi.x = res[4] + Sbuf[lane * 8 + 4][rloc];
        ohi.y = res[5] + Sbuf[lane * 8 + 5][rloc];
        ohi.z = res[6] + Sbuf[lane * 8 + 6][rloc];
        ohi.w = res[7] + Sbuf[lane * 8 + 7][rloc];
        *(float4*)&out[ob + ro]     = olo;
        *(float4*)&out[ob + ro + 4] = ohi;
    }
}

// ---------------------------------------------------------------------------
extern "C" void kernel_launch(void* const* d_in, const int* in_sizes, int n_in,
                              void* d_out, int out_size)
{
    const float* xs = (const float*)d_in[0];

    ConvParams P;
    for (int s = 0; s < 3; ++s) {
        int base = 1 + s * 5;
        P.w[s] = (const float*)d_in[base + 0];
        P.g[s] = (const float*)d_in[base + 1];
        P.b[s] = (const float*)d_in[base + 2];
        P.m[s] = (const float*)d_in[base + 3];
        P.v[s] = (const float*)d_in[base + 4];
    }
    const float* h20 = (const float*)d_in[16];
    const float* h21 = (const float*)d_in[17];
    const float* h30 = (const float*)d_in[18];
    const float* h31 = (const float*)d_in[19];

    float* out = (float*)d_out;

    cudaFuncSetAttribute(conv_mma_kernel,
                         cudaFuncAttributeMaxDynamicSharedMemorySize, SMEM_BYTES);

    dim3 xgrid(2, 256, 4);
    xpose_kernel<<<xgrid, 256>>>(xs);

    prep_kernel<<<1728, 256>>>(P);

    dim3 cgrid(512, 6, 4);
    conv_mma_kernel<<<cgrid, 256, SMEM_BYTES>>>();

    segscan_v_kernel<<<4096, 256>>>();
    scan_tail_kernel<<<2048, 256>>>(h20, h21, h30, h31, out);
}

// round 10
// speedup vs baseline: 8.3175x; 1.0236x over previous
#include <cuda_runtime.h>
#include <cuda_fp16.h>
#include <math.h>
#include <stdint.h>

// ---------------------------------------------------------------------------
// MiniGRUConv2d4 on GB300 (compute_103 PTX target -> legacy mma.sync path):
//   pass 1: transpose xs -> xh[b][y][x][ci] fp16
//   pass 2: 3x(conv3x3+BN[+sigmoid]) implicit GEMM, fp16 mma.sync.m16n8k16,
//           ldmatrix fragment loads, progressive halo staging, weights via
//           cp.async ring. ALL planes (z, h, s) stored fp16.
//   pass 3: vertical scans: segment compose + fused apply/horizontal tail.
// ---------------------------------------------------------------------------

#define B_  4
#define CIN 64
#define C4  256

static __device__ __half gH[(size_t)B_ * C4 * 256 * 256];            // h plane
static __device__ __half gZ[(size_t)B_ * C4 * 256 * 256];            // z plane
static __device__ __half gS[(size_t)B_ * C4 * 256 * 256];            // s plane
static __device__ __align__(16) __half gXh[(size_t)B_ * 256 * 256 * 64];
static __device__ __align__(16) __half gWtH[768 * 576];
static __device__ float gBias[768];
static __device__ float2 gSeg[2 * 4 * 64 * 8 * 256];                 // seg (A,B)

struct ConvParams {
    const float* w[3];
    const float* g[3];
    const float* b[3];
    const float* m[3];
    const float* v[3];
};

// ---------------- fast sigmoid (no MUFU) ------------------------------------
__device__ __forceinline__ float fast_sigmoid(float x)
{
    float u = -1.44269504f * x;
    u = fminf(fmaxf(u, -60.f), 60.f);
    float fi = rintf(u);
    float f  = u - fi;
    float p = 1.54035304e-4f;
    p = fmaf(p, f, 1.33335581e-3f);
    p = fmaf(p, f, 9.61812910e-3f);
    p = fmaf(p, f, 5.55041087e-2f);
    p = fmaf(p, f, 2.40226507e-1f);
    p = fmaf(p, f, 6.93147181e-1f);
    p = fmaf(p, f, 1.0f);
    int ei = (int)fi;
    float e = __int_as_float(__float_as_int(p) + (ei << 23));
    float d = 1.0f + e;
    float r = __int_as_float(0x7EF311C3 - __float_as_int(d));
    r = r * (2.0f - d * r);
    r = r * (2.0f - d * r);
    r = r * (2.0f - d * r);
    return r;
}

// ---------------- small helpers ---------------------------------------------
__device__ __forceinline__ uint32_t smem_u32(const void* p)
{
    uint32_t a;
    asm("{ .reg .u64 t; cvta.to.shared.u64 t, %1; cvt.u32.u64 %0, t; }"
        : "=r"(a) : "l"(p));
    return a;
}
__device__ __forceinline__ void cp16(uint32_t dst, const void* src)
{
    size_t g = __cvta_generic_to_global(src);
    asm volatile("cp.async.cg.shared.global [%0], [%1], 16;"
                 :: "r"(dst), "l"(g) : "memory");
}
__device__ __forceinline__ void sts_zero16(uint32_t a)
{
    asm volatile("st.shared.v4.u32 [%0], {%1,%1,%1,%1};" :: "r"(a), "r"(0u) : "memory");
}
__device__ __forceinline__ void ldsm_x4(uint32_t& r0, uint32_t& r1,
                                        uint32_t& r2, uint32_t& r3, uint32_t a)
{
    asm volatile("ldmatrix.sync.aligned.m8n8.x4.shared.b16 {%0,%1,%2,%3}, [%4];"
                 : "=r"(r0), "=r"(r1), "=r"(r2), "=r"(r3) : "r"(a));
}
// load 8 consecutive halves -> 8 floats
__device__ __forceinline__ void ld8h(const __half* p, float* d)
{
    uint4 u = *(const uint4*)p;
    const __half2* h = (const __half2*)&u;
    float2 f0 = __half22float2(h[0]);
    float2 f1 = __half22float2(h[1]);
    float2 f2 = __half22float2(h[2]);
    float2 f3 = __half22float2(h[3]);
    d[0] = f0.x; d[1] = f0.y; d[2] = f1.x; d[3] = f1.y;
    d[4] = f2.x; d[5] = f2.y; d[6] = f3.x; d[7] = f3.y;
}

// ---------------------------------------------------------------------------
// Prep: fold BN into fp16 weights, k = r*64+ci ordering; fp32 bias.
// ---------------------------------------------------------------------------
__global__ void prep_kernel(ConvParams P)
{
    int idx = blockIdx.x * 256 + threadIdx.x;
    if (idx < 768) {
        int set = idx >> 8, co = idx & 255;
        float inv = P.g[set][co] * rsqrtf(P.v[set][co] + 1e-5f);
        gBias[idx] = P.b[set][co] - P.m[set][co] * inv;
    }
    if (idx < 768 * 576) {
        int co_g = idx / 576;
        int k    = idx - co_g * 576;
        int r    = k >> 6;
        int ci   = k & 63;
        int set  = co_g >> 8;
        int co   = co_g & 255;
        float inv = P.g[set][co] * rsqrtf(P.v[set][co] + 1e-5f);
        gWtH[idx] = __float2half_rn(P.w[set][(co * 64 + ci) * 9 + r] * inv);
    }
}

// ---------------------------------------------------------------------------
// Transpose xs [b][ci][y][x] fp32 -> gXh [b][y][x][ci] fp16.
// ---------------------------------------------------------------------------
__global__ __launch_bounds__(256)
void xpose_kernel(const float* __restrict__ xs)
{
    __shared__ float S[64][129];
    const int xt = blockIdx.x;
    const int y  = blockIdx.y;
    const int b  = blockIdx.z;
    const int tid = threadIdx.x;

    const float* src = xs + (((size_t)b * CIN) << 16) + (y << 8) + xt * 128;
#pragma unroll
    for (int p = 0; p < 8; ++p) {
        int idx = tid + (p << 8);
        int ci  = idx >> 5;
        int x4  = idx & 31;
        float4 v = *(const float4*)(src + (((size_t)ci) << 16) + (x4 << 2));
        S[ci][x4 * 4 + 0] = v.x;
        S[ci][x4 * 4 + 1] = v.y;
        S[ci][x4 * 4 + 2] = v.z;
        S[ci][x4 * 4 + 3] = v.w;
    }
    __syncthreads();

    __half* dst = gXh + ((((size_t)b * 256 + y) * 256) + xt * 128) * 64;
#pragma unroll
    for (int p = 0; p < 4; ++p) {
        int chunk = tid + (p << 8);
        int g = chunk & 7;
        int x = chunk >> 3;
        int c0 = g * 8;
        __half2 h0 = __floats2half2_rn(S[c0 + 0][x], S[c0 + 1][x]);
        __half2 h1 = __floats2half2_rn(S[c0 + 2][x], S[c0 + 3][x]);
        __half2 h2 = __floats2half2_rn(S[c0 + 4][x], S[c0 + 5][x]);
        __half2 h3 = __floats2half2_rn(S[c0 + 6][x], S[c0 + 7][x]);
        uint4 val;
        val.x = *(uint32_t*)&h0; val.y = *(uint32_t*)&h1;
        val.z = *(uint32_t*)&h2; val.w = *(uint32_t*)&h3;
        *(uint4*)(dst + (size_t)x * 64 + g * 8) = val;
    }
}

// ---------------------------------------------------------------------------
// Conv: CTA = 128 px x 128 couts, 8 warps (4m x 2n), warp 32co x 64px.
// ldmatrix fragment loads; progressive halo staging; 2 CTAs/SM.
// ---------------------------------------------------------------------------
#define BT_STRIDE 132
#define BT_BYTES  (3 * BT_STRIDE * 128)          // 50688
#define A_BUF     8192
#define SMEM_BYTES (BT_BYTES + 4 * A_BUF)        // 83456

__global__ __launch_bounds__(256, 2)
void conv_mma_kernel()
{
    extern __shared__ char smem[];
    const uint32_t sB = smem_u32(smem);
    const uint32_t sA = sB + BT_BYTES;

    const int tid = threadIdx.x;
    const int l   = tid & 31;
    const int w   = tid >> 5;
    const int wm  = w >> 1;            // 0..3 (32 co each)
    const int wn  = w & 1;             // 0..1 (64 px each)

    const int bx = blockIdx.x;         // 0..511
    const int y0 = bx >> 1;
    const int x0 = (bx & 1) << 7;
    const int m0 = blockIdx.y << 7;    // 0..640
    const int b  = blockIdx.z;

    // ---- A ring producer: 128co x 32k fp16 per chunk ----
    auto issueA = [&](int kt2) {
        if (kt2 < 18) {
            uint32_t base = sA + (uint32_t)((kt2 & 3) * A_BUF);
            const __half* src = gWtH + (size_t)m0 * 576 + kt2 * 32;
#pragma unroll
            for (int p = 0; p < 2; ++p) {
                int chunk = tid + (p << 8);
                int co  = chunk >> 2;
                int kpg = chunk & 3;
                uint32_t wrd = (uint32_t)(co << 4)
                             + (uint32_t)((kpg ^ ((co >> 1) & 3)) << 2);
                cp16(base + (wrd << 2), src + (size_t)co * 576 + (kpg << 3));
            }
        }
        asm volatile("cp.async.commit_group;" ::: "memory");
    };

    // ---- progressive B halo fill: row r goes in cp.async group r ----
    for (int row = 0; row < 3; ++row) {
        const int y = y0 - 1 + row;
        const bool rok = (unsigned)y < 256u;
        for (int t = tid; t < 1040; t += 256) {
            int slot = t >> 3;
            int g    = t & 7;
            int x    = x0 + slot - 1;
            uint32_t dst = sB + (uint32_t)(row * BT_STRIDE + slot) * 128
                         + (uint32_t)((g ^ (slot & 7)) << 4);
            if (rok && (unsigned)x < 256u)
                cp16(dst, gXh + ((((size_t)b * 256 + y) * 256 + x) * 64 + g * 8));
            else
                sts_zero16(dst);
        }
        issueA(row);
    }

    // ---- per-lane ldmatrix address constants ----
    const int hiA   = l >> 4;
    const int cA0   = (wm << 5) + (l & 15);
    const int cA1   = cA0 + 16;
    const int xa0   = (cA0 >> 1) & 3;
    const int xa1   = (cA1 >> 1) & 3;
    const uint32_t aoff0 = (uint32_t)(cA0 << 6);
    const uint32_t aoff1 = (uint32_t)(cA1 << 6);
    const int gsel  = (l >> 3) & 1;
    const int sbl   = (wn << 6) + (l & 7) + ((l >> 4) << 3);

    float acc[2][8][4];
#pragma unroll
    for (int mt = 0; mt < 2; ++mt)
#pragma unroll
        for (int nt = 0; nt < 8; ++nt)
#pragma unroll
            for (int c = 0; c < 4; ++c) acc[mt][nt][c] = 0.f;

    for (int kt = 0; kt < 18; ++kt) {
        asm volatile("cp.async.wait_group 2;" ::: "memory");
        __syncthreads();

        const uint32_t abuf = sA + (uint32_t)((kt & 3) * A_BUF);
        const int r   = kt >> 1;
        const int row = r / 3;
        const int dxp = r - row * 3;
        const uint32_t rowbase = sB + (uint32_t)(row * BT_STRIDE) * 128;

#pragma unroll
        for (int ks = 0; ks < 2; ++ks) {
            const int kg = (ks << 1) + hiA;
            uint32_t a0[4], a1[4];
            ldsm_x4(a0[0], a0[1], a0[2], a0[3],
                    abuf + aoff0 + (uint32_t)((kg ^ xa0) << 4));
            ldsm_x4(a1[0], a1[1], a1[2], a1[3],
                    abuf + aoff1 + (uint32_t)((kg ^ xa1) << 4));

            const int ga = ((kt & 1) << 2) + (ks << 1) + gsel;
#pragma unroll
            for (int ntp = 0; ntp < 4; ++ntp) {
                int slot = sbl + (ntp << 4) + dxp;
                uint32_t addr = rowbase + (uint32_t)(slot << 7)
                              + (uint32_t)((ga ^ (slot & 7)) << 4);
                uint32_t b0, b1, b2, b3;
                ldsm_x4(b0, b1, b2, b3, addr);

                const int nt0 = ntp << 1;
#pragma unroll
                for (int half = 0; half < 2; ++half) {
                    uint32_t bb0 = half ? b2 : b0;
                    uint32_t bb1 = half ? b3 : b1;
                    int nt = nt0 + half;
                    asm volatile(
                        "mma.sync.aligned.m16n8k16.row.col.f32.f16.f16.f32 "
                        "{%0,%1,%2,%3}, {%4,%5,%6,%7}, {%8,%9}, {%0,%1,%2,%3};"
                        : "+f"(acc[0][nt][0]), "+f"(acc[0][nt][1]),
                          "+f"(acc[0][nt][2]), "+f"(acc[0][nt][3])
                        : "r"(a0[0]), "r"(a0[1]), "r"(a0[2]), "r"(a0[3]),
                          "r"(bb0), "r"(bb1));
                    asm volatile(
                        "mma.sync.aligned.m16n8k16.row.col.f32.f16.f16.f32 "
                        "{%0,%1,%2,%3}, {%4,%5,%6,%7}, {%8,%9}, {%0,%1,%2,%3};"
                        : "+f"(acc[1][nt][0]), "+f"(acc[1][nt][1]),
                          "+f"(acc[1][nt][2]), "+f"(acc[1][nt][3])
                        : "r"(a1[0]), "r"(a1[1]), "r"(a1[2]), "r"(a1[3]),
                          "r"(bb0), "r"(bb1));
                }
            }
        }
        issueA(kt + 3);
    }

    // ---- epilogue: bias; all sets -> fp16 planes (sigmoid for sets 0/2) ----
    const int set = m0 >> 8;
    const int chb = m0 & 255;
#pragma unroll
    for (int mt = 0; mt < 2; ++mt) {
#pragma unroll
        for (int rr = 0; rr < 2; ++rr) {
            int cloc = (wm << 5) + (mt << 4) + (l >> 2) + (rr << 3);
            float bias = gBias[m0 + cloc];
            int ch = chb + cloc;
            size_t base = (((size_t)b * C4 + ch) << 16) + ((size_t)y0 << 8) + x0;
#pragma unroll
            for (int nt = 0; nt < 8; ++nt) {
                int n = (wn << 6) + (nt << 3) + ((l & 3) << 1);
                float v0 = acc[mt][nt][rr * 2 + 0] + bias;
                float v1 = acc[mt][nt][rr * 2 + 1] + bias;
                if (set == 1) {
                    *(__half2*)&gH[base + n] = __floats2half2_rn(v0, v1);
                } else {
                    __half2 h2 = __floats2half2_rn(fast_sigmoid(v0),
                                                   fast_sigmoid(v1));
                    if (set == 0) *(__half2*)&gZ[base + n] = h2;
                    else          *(__half2*)&gS[base + n] = h2;
                }
            }
        }
    }
}

// ---------------------------------------------------------------------------
// Vertical scan phase A: per-segment affine composition (A,B) over 32 rows.
// grid: 4096 blocks x 256 thr; block = seg(8) | c(64) | b(4) | g(2).
// ---------------------------------------------------------------------------
__global__ __launch_bounds__(256)
void segscan_v_kernel()
{
    const int x   = threadIdx.x;
    const int blk = blockIdx.x;
    const int seg = blk & 7;
    const int c   = (blk >> 3) & 63;
    const int b   = (blk >> 9) & 3;
    const int g   = blk >> 11;

    const size_t pb = (((size_t)b * C4 + g * 64 + c) << 16) + x;

    float A = 1.f, Bv = 0.f;
    const int ybase = seg << 5;
    if (g == 0) {
#pragma unroll 8
        for (int i = 0; i < 32; ++i) {
            size_t off = (size_t)(ybase + i) << 8;
            float z  = __half2float(gZ[pb + off]);
            float hv = __half2float(gH[pb + off]);
            float ai = 1.f - z;
            Bv = fmaf(ai, Bv, z * hv);
            A  = A * ai;
        }
    } else {
#pragma unroll 8
        for (int i = 31; i >= 0; --i) {
            size_t off = (size_t)(ybase + i) << 8;
            float z  = __half2float(gZ[pb + off]);
            float hv = __half2float(gH[pb + off]);
            float ai = 1.f - z;
            Bv = fmaf(ai, Bv, z * hv);
            A  = A * ai;
        }
    }
    gSeg[(size_t)blk * 256 + x] = make_float2(A, Bv);
}

// ---------------------------------------------------------------------------
// Fused tail: vertical apply (groups 0,1) into smem, then horizontal scans
// (groups 2,3) per row, single write of out. Block = seg(8) | c(64) | b(4).
// ---------------------------------------------------------------------------
__global__ __launch_bounds__(256)
void scan_tail_kernel(const float* __restrict__ h20,
                      const float* __restrict__ h21,
                      const float* __restrict__ h30,
                      const float* __restrict__ h31,
                      float* __restrict__ out)
{
    __shared__ float Sbuf[256][33];

    const int blk = blockIdx.x;
    const int seg = blk & 7;
    const int c   = (blk >> 3) & 63;
    const int b   = blk >> 9;
    const int tid = threadIdx.x;
    const int warp = tid >> 5;
    const int lane = tid & 31;

    // ================= part 1: vertical apply for column x = tid ===========
    {
        const int x = tid;
        float st0 = h20[c];
        {
            const size_t base = ((size_t)((0 * 4 + b) * 64 + c) * 8) * 256 + x;
            for (int k = 0; k < seg; ++k) {
                float2 f = gSeg[base + (size_t)k * 256];
                st0 = fmaf(f.x, st0, f.y);
            }
        }
        float st1 = h21[c];
        {
            const size_t base = ((size_t)((1 * 4 + b) * 64 + c) * 8) * 256 + x;
            for (int k = 7; k > seg; --k) {
                float2 f = gSeg[base + (size_t)k * 256];
                st1 = fmaf(f.x, st1, f.y);
            }
        }

        const int ybase = seg << 5;
        const size_t p0 = (((size_t)b * C4 + c) << 16) + x;         // group 0
        const size_t p1 = p0 + ((size_t)64 << 16);                  // group 1

#pragma unroll
        for (int i = 0; i < 32; ++i) {
            size_t off = (size_t)(ybase + i) << 8;
            float z  = __half2float(gZ[p0 + off]);
            float hv = __half2float(gH[p0 + off]);
            float s  = __half2float(gS[p0 + off]);
            st0 = z * hv + (1.f - z) * st0;
            Sbuf[x][i] = s * st0;
        }
#pragma unroll
        for (int i = 31; i >= 0; --i) {
            size_t off = (size_t)(ybase + i) << 8;
            float z  = __half2float(gZ[p1 + off]);
            float hv = __half2float(gH[p1 + off]);
            float s  = __half2float(gS[p1 + off]);
            st1 = z * hv + (1.f - z) * st1;
            Sbuf[x][i] += s * st1;
        }
    }
    __syncthreads();

    // ================= part 2: horizontal scans, rows of this seg ==========
    const float hi30 = h30[c];
    const float hi31 = h31[c];
    const size_t p2 = ((size_t)b * C4 + 128 + c) << 16;             // group 2
    const size_t p3 = ((size_t)b * C4 + 192 + c) << 16;             // group 3
    const size_t ob = ((size_t)b * 64 + c) << 16;

    for (int rr = 0; rr < 4; ++rr) {
        const int rloc = warp * 4 + rr;                 // 0..31
        const int y = (seg << 5) + rloc;
        const size_t ro = ((size_t)y << 8) + lane * 8;

        float res[8];

        // ---- group 2: forward scan ----
        {
            float zz[8], qq[8], ss[8];
            ld8h(&gZ[p2 + ro], zz);
            ld8h(&gH[p2 + ro], qq);
            float A[8], Bv[8];
            float ra = 1.f, rb = 0.f;
#pragma unroll
            for (int i = 0; i < 8; ++i) {
                float ai = 1.f - zz[i];
                float bi = zz[i] * qq[i];
                rb = fmaf(ai, rb, bi);
                ra = ra * ai;
                A[i] = ra; Bv[i] = rb;
            }
            float ga = ra, gb = rb;
#pragma unroll
            for (int off = 1; off < 32; off <<= 1) {
                float pa = __shfl_up_sync(0xFFFFFFFFu, ga, off);
                float pb = __shfl_up_sync(0xFFFFFFFFu, gb, off);
                if (lane >= off) { gb = fmaf(ga, pb, gb); ga = ga * pa; }
            }
            float PA = __shfl_up_sync(0xFFFFFFFFu, ga, 1);
            float PB = __shfl_up_sync(0xFFFFFFFFu, gb, 1);
            if (lane == 0) { PA = 1.f; PB = 0.f; }
            float base = fmaf(PA, hi30, PB);
            ld8h(&gS[p2 + ro], ss);
#pragma unroll
            for (int i = 0; i < 8; ++i)
                res[i] = ss[i] * fmaf(A[i], base, Bv[i]);
        }

        // ---- group 3: reverse scan ----
        {
            float zz[8], qq[8], ss[8];
            ld8h(&gZ[p3 + ro], zz);
            ld8h(&gH[p3 + ro], qq);
            float A[8], Bv[8];
            float ra = 1.f, rb = 0.f;
#pragma unroll
            for (int i = 7; i >= 0; --i) {
                float ai = 1.f - zz[i];
                float bi = zz[i] * qq[i];
                rb = fmaf(ai, rb, bi);
                ra = ra * ai;
                A[i] = ra; Bv[i] = rb;
            }
            float ga = ra, gb = rb;
#pragma unroll
            for (int off = 1; off < 32; off <<= 1) {
                float pa = __shfl_down_sync(0xFFFFFFFFu, ga, off);
                float pb = __shfl_down_sync(0xFFFFFFFFu, gb, off);
                if (lane + off < 32) { gb = fmaf(ga, pb, gb); ga = ga * pa; }
            }
            float PA = __shfl_down_sync(0xFFFFFFFFu, ga, 1);
            float PB = __shfl_down_sync(0xFFFFFFFFu, gb, 1);
            if (lane == 31) { PA = 1.f; PB = 0.f; }
            float base = fmaf(PA, hi31, PB);
            ld8h(&gS[p3 + ro], ss);
#pragma unroll
            for (int i = 0; i < 8; ++i)
                res[i] += ss[i] * fmaf(A[i], base, Bv[i]);
        }

        // ---- add vertical part from smem, single store ----
        float4 olo, ohi;
        olo.x = res[0] + Sbuf[lane * 8 + 0][rloc];
        olo.y = res[1] + Sbuf[lane * 8 + 1][rloc];
        olo.z = res[2] + Sbuf[lane * 8 + 2][rloc];
        olo.w = res[3] + Sbuf[lane * 8 + 3][rloc];
        ohi.x = res[4] + Sbuf[lane * 8 + 4][rloc];
        ohi.y = res[5] + Sbuf[lane * 8 + 5][rloc];
        ohi.z = res[6] + Sbuf[lane * 8 + 6][rloc];
        ohi.w = res[7] + Sbuf[lane * 8 + 7][rloc];
        *(float4*)&out[ob + ro]     = olo;
        *(float4*)&out[ob + ro + 4] = ohi;
    }
}

// ---------------------------------------------------------------------------
extern "C" void kernel_launch(void* const* d_in, const int* in_sizes, int n_in,
                              void* d_out, int out_size)
{
    const float* xs = (const float*)d_in[0];

    ConvParams P;
    for (int s = 0; s < 3; ++s) {
        int base = 1 + s * 5;
        P.w[s] = (const float*)d_in[base + 0];
        P.g[s] = (const float*)d_in[base + 1];
        P.b[s] = (const float*)d_in[base + 2];
        P.m[s] = (const float*)d_in[base + 3];
        P.v[s] = (const float*)d_in[base + 4];
    }
    const float* h20 = (const float*)d_in[16];
    const float* h21 = (const float*)d_in[17];
    const float* h30 = (const float*)d_in[18];
    const float* h31 = (const float*)d_in[19];

    float* out = (float*)d_out;

    cudaFuncSetAttribute(conv_mma_kernel,
                         cudaFuncAttributeMaxDynamicSharedMemorySize, SMEM_BYTES);

    dim3 xgrid(2, 256, 4);
    xpose_kernel<<<xgrid, 256>>>(xs);

    prep_kernel<<<1728, 256>>>(P);

    dim3 cgrid(512, 6, 4);
    conv_mma_kernel<<<cgrid, 256, SMEM_BYTES>>>();

    segscan_v_kernel<<<4096, 256>>>();
    scan_tail_kernel<<<2048, 256>>>(h20, h21, h30, h31, out);
}